// round 1
// baseline (speedup 1.0000x reference)
#include <cuda_runtime.h>
#include <cuda_bf16.h>
#include <cstddef>

#define N_NODES 100000
#define N_EDGES 3200000
#define F_IN    256
#define F_OUT   64
#define NF      (N_NODES * F_OUT)

// Scratch (device globals; allocation-free).
__device__ float g_s0[NF];
__device__ float g_acc[6][NF];   // hA, hA2, hA3, hs1, hs2, hs3

// ---------------------------------------------------------------------------
// GEMM: s0[N,64] = x[N,256] @ W[256,64], fp32.
// Block = 128 threads, 64 rows x 64 cols per block; each thread 4 rows x 8 cols.
// ---------------------------------------------------------------------------
__global__ void gemm64(const float* __restrict__ x, const float* __restrict__ W,
                       float* __restrict__ out)
{
    __shared__ float xs[32][64];   // transposed: xs[kk][row]
    __shared__ float ws[32][64];   // ws[kk][col]

    const int tid = threadIdx.x;       // 0..127
    const int tx  = tid & 7;           // col octant
    const int ty  = tid >> 3;          // 0..15 (4 rows each)
    const int r0  = blockIdx.x * 64;

    float4 acc0[4] = {};
    float4 acc1[4] = {};

    for (int k0 = 0; k0 < F_IN; k0 += 32) {
        // load x tile (transpose into xs)
        #pragma unroll
        for (int it = 0; it < 4; it++) {
            int li  = it * 128 + tid;     // 0..511
            int row = li >> 3;            // 0..63
            int kq  = li & 7;             // 0..7
            float4 v = make_float4(0.f, 0.f, 0.f, 0.f);
            int gr = r0 + row;
            if (gr < N_NODES)
                v = *(const float4*)(x + (size_t)gr * F_IN + k0 + kq * 4);
            xs[kq * 4 + 0][row] = v.x;
            xs[kq * 4 + 1][row] = v.y;
            xs[kq * 4 + 2][row] = v.z;
            xs[kq * 4 + 3][row] = v.w;
        }
        // load W tile
        #pragma unroll
        for (int it = 0; it < 4; it++) {
            int li = it * 128 + tid;      // 0..511
            int kk = li >> 4;             // 0..31
            int cq = li & 15;             // 0..15
            *(float4*)&ws[kk][cq * 4] =
                *(const float4*)(W + (size_t)(k0 + kk) * F_OUT + cq * 4);
        }
        __syncthreads();

        #pragma unroll
        for (int kk = 0; kk < 32; kk++) {
            float4 av = *(const float4*)&xs[kk][ty * 4];
            float4 b0 = *(const float4*)&ws[kk][tx * 4];
            float4 b1 = *(const float4*)&ws[kk][tx * 4 + 32];
            float a4[4] = {av.x, av.y, av.z, av.w};
            #pragma unroll
            for (int j = 0; j < 4; j++) {
                acc0[j].x = fmaf(a4[j], b0.x, acc0[j].x);
                acc0[j].y = fmaf(a4[j], b0.y, acc0[j].y);
                acc0[j].z = fmaf(a4[j], b0.z, acc0[j].z);
                acc0[j].w = fmaf(a4[j], b0.w, acc0[j].w);
                acc1[j].x = fmaf(a4[j], b1.x, acc1[j].x);
                acc1[j].y = fmaf(a4[j], b1.y, acc1[j].y);
                acc1[j].z = fmaf(a4[j], b1.z, acc1[j].z);
                acc1[j].w = fmaf(a4[j], b1.w, acc1[j].w);
            }
        }
        __syncthreads();
    }

    #pragma unroll
    for (int j = 0; j < 4; j++) {
        int gr = r0 + ty * 4 + j;
        if (gr < N_NODES) {
            *(float4*)(out + (size_t)gr * F_OUT + tx * 4)      = acc0[j];
            *(float4*)(out + (size_t)gr * F_OUT + tx * 4 + 32) = acc1[j];
        }
    }
}

// ---------------------------------------------------------------------------
// SPMM (COO, scatter with vector atomics): out[r] += v * in[c]
// Block 256 threads stages 256 edges into smem; each warp handles 32 edges,
// 2 edges per iteration (16 lanes x float4 = 64 features each).
// ---------------------------------------------------------------------------
__global__ void spmm_atomic(const int* __restrict__ eidx, const float* __restrict__ eval,
                            const float* __restrict__ in, float* __restrict__ out)
{
    __shared__ int   sr[256];
    __shared__ int   sc[256];
    __shared__ float sv[256];

    const int tid = threadIdx.x;
    const int e   = blockIdx.x * 256 + tid;
    if (e < N_EDGES) {
        sr[tid] = eidx[e];              // destination row = idx[0]
        sc[tid] = eidx[N_EDGES + e];    // source col      = idx[1]
        sv[tid] = eval[e];
    } else {
        sr[tid] = -1;
    }
    __syncthreads();

    const int lane = tid & 31;
    const int warp = tid >> 5;
    const int half = lane >> 4;            // 0 or 1 (which edge of the pair)
    const int fq   = (lane & 15) * 4;      // feature offset (float4)

    #pragma unroll
    for (int jj = 0; jj < 32; jj += 2) {
        int ei = warp * 32 + jj + half;
        int r  = sr[ei];
        if (r >= 0) {
            int   c = sc[ei];
            float v = sv[ei];
            float4 xv = *(const float4*)(in + (size_t)c * F_OUT + fq);
            float px = v * xv.x, py = v * xv.y, pz = v * xv.z, pw = v * xv.w;
            asm volatile("red.global.add.v4.f32 [%0], {%1,%2,%3,%4};"
                         :: "l"(out + (size_t)r * F_OUT + fq),
                            "f"(px), "f"(py), "f"(pz), "f"(pw)
                         : "memory");
        }
    }
}

// ---------------------------------------------------------------------------
// Finalize: e (raw-reshape semantics), softmax, permuted channel-mean h_prime.
// Block 256 = 8 warps; one node per warp.
// ---------------------------------------------------------------------------
__global__ void finalize(const float* __restrict__ s0, const float* __restrict__ a,
                         float* __restrict__ out_hp, float* __restrict__ out_att)
{
    __shared__ float ch[8][6][64];
    __shared__ float as[768];

    const int tid = threadIdx.x;
    for (int i = tid; i < 768; i += 256) as[i] = a[i];

    const int w    = tid >> 5;
    const int lane = tid & 31;
    const int r    = blockIdx.x * 8 + w;   // 100000 = 12500 * 8, exact
    __syncthreads();

    // stage this node's 6 channel rows (abs applied to channels 3..5)
    #pragma unroll
    for (int c = 0; c < 6; c++) {
        float v0 = g_acc[c][(size_t)r * F_OUT + lane];
        float v1 = g_acc[c][(size_t)r * F_OUT + lane + 32];
        if (c >= 3) { v0 = fabsf(v0); v1 = fabsf(v1); }
        ch[w][c][lane]      = v0;
        ch[w][c][lane + 32] = v1;
    }
    __syncwarp();

    // e[r,i] via the cat(dim=0).view(N,2F) raw reshape
    float p[6];
    if (r < N_NODES / 2) {
        size_t b0 = (size_t)(2 * r) * F_OUT;
        size_t b1 = (size_t)(2 * r + 1) * F_OUT;
        float u0 = s0[b0 + lane], u1 = s0[b0 + lane + 32];
        float w0 = s0[b1 + lane], w1 = s0[b1 + lane + 32];
        #pragma unroll
        for (int i = 0; i < 6; i++) {
            const float* ai = as + i * 128;
            p[i] = ai[lane] * u0 + ai[lane + 32] * u1
                 + ai[64 + lane] * w0 + ai[96 + lane] * w1;
        }
    } else {
        int q = 2 * r - N_NODES;
        #pragma unroll
        for (int i = 0; i < 6; i++) {
            float u0 = g_acc[i][(size_t)q * F_OUT + lane];
            float u1 = g_acc[i][(size_t)q * F_OUT + lane + 32];
            float w0 = g_acc[i][(size_t)(q + 1) * F_OUT + lane];
            float w1 = g_acc[i][(size_t)(q + 1) * F_OUT + lane + 32];
            if (i >= 3) { u0 = fabsf(u0); u1 = fabsf(u1); w0 = fabsf(w0); w1 = fabsf(w1); }
            const float* ai = as + i * 128;
            p[i] = ai[lane] * u0 + ai[lane + 32] * u1
                 + ai[64 + lane] * w0 + ai[96 + lane] * w1;
        }
    }

    // warp-reduce the 6 dot products, broadcast
    #pragma unroll
    for (int i = 0; i < 6; i++) {
        #pragma unroll
        for (int off = 16; off; off >>= 1)
            p[i] += __shfl_down_sync(0xffffffffu, p[i], off);
        p[i] = __shfl_sync(0xffffffffu, p[i], 0);
    }

    // softmax over 6 channels
    float m = p[0];
    #pragma unroll
    for (int i = 1; i < 6; i++) m = fmaxf(m, p[i]);
    float att[6], s = 0.f;
    #pragma unroll
    for (int i = 0; i < 6; i++) { att[i] = expf(p[i] - m); s += att[i]; }
    float inv = 1.f / s;
    #pragma unroll
    for (int i = 0; i < 6; i++) att[i] *= inv;

    if (out_att && lane == 0) {
        #pragma unroll
        for (int i = 0; i < 6; i++) out_att[(size_t)r * 6 + i] = att[i];
    }

    // h_prime[r,k] = (1/6) sum_j att[j] * chans[(64j+k)%6][r,(64j+k)/6]
    #pragma unroll
    for (int kk = 0; kk < 2; kk++) {
        int k = lane + kk * 32;
        float hp = 0.f;
        #pragma unroll
        for (int j = 0; j < 6; j++) {
            int idx = j * 64 + k;
            int c = idx % 6;
            int f = idx / 6;
            hp = fmaf(att[j], ch[w][c][f], hp);
        }
        out_hp[(size_t)r * F_OUT + k] = hp * (1.0f / 6.0f);
    }
}

// ---------------------------------------------------------------------------
extern "C" void kernel_launch(void* const* d_in, const int* in_sizes, int n_in,
                              void* d_out, int out_size)
{
    const float* x      = (const float*)d_in[0];
    const float* W      = (const float*)d_in[1];
    const float* a      = (const float*)d_in[2];
    const int*   A_idx  = (const int*)  d_in[3];
    const float* A_val  = (const float*)d_in[4];
    const int*   P1_idx = (const int*)  d_in[5];
    const float* P1_val = (const float*)d_in[6];
    const int*   P2_idx = (const int*)  d_in[7];
    const float* P2_val = (const float*)d_in[8];
    const int*   P3_idx = (const int*)  d_in[9];
    const float* P3_val = (const float*)d_in[10];

    float* s0  = nullptr;
    float* acc = nullptr;
    cudaGetSymbolAddress((void**)&s0,  g_s0);
    cudaGetSymbolAddress((void**)&acc, g_acc);

    // zero the 6 atomic accumulators
    cudaMemsetAsync(acc, 0, sizeof(float) * 6 * (size_t)NF, 0);

    gemm64<<<(N_NODES + 63) / 64, 128>>>(x, W, s0);

    const int SPMM_GRID = (N_EDGES + 255) / 256;
    spmm_atomic<<<SPMM_GRID, 256>>>(A_idx,  A_val,  s0,            acc + 0 * (size_t)NF);
    spmm_atomic<<<SPMM_GRID, 256>>>(A_idx,  A_val,  acc + 0 * (size_t)NF, acc + 1 * (size_t)NF);
    spmm_atomic<<<SPMM_GRID, 256>>>(A_idx,  A_val,  acc + 1 * (size_t)NF, acc + 2 * (size_t)NF);
    spmm_atomic<<<SPMM_GRID, 256>>>(P1_idx, P1_val, s0,            acc + 3 * (size_t)NF);
    spmm_atomic<<<SPMM_GRID, 256>>>(P2_idx, P2_val, s0,            acc + 4 * (size_t)NF);
    spmm_atomic<<<SPMM_GRID, 256>>>(P3_idx, P3_val, s0,            acc + 5 * (size_t)NF);

    float* out = (float*)d_out;
    float* att = (out_size >= N_NODES * F_OUT + N_NODES * 6)
                     ? out + (size_t)N_NODES * F_OUT : nullptr;
    finalize<<<N_NODES / 8, 256>>>(s0, a, out, att);
}

// round 2
// speedup vs baseline: 1.1476x; 1.1476x over previous
#include <cuda_runtime.h>
#include <cuda_bf16.h>
#include <cstddef>

#define N_NODES 100000
#define N_EDGES 3200000
#define F_IN    256
#define F_OUT   64
#define NF      (N_NODES * F_OUT)
#define SCAN_BLK 1024
#define NB_SCAN  ((N_NODES + SCAN_BLK - 1) / SCAN_BLK)   // 98

// Scratch (device globals; allocation-free).
__device__ float g_s0[NF];
__device__ float g_acc[6][NF];           // hA, hA2, hA3, hs1, hs2, hs3
__device__ int   g_cnt[4][N_NODES];      // per-op row histograms
__device__ int   g_rowptr[4][N_NODES + 1];
__device__ int   g_cursor[4][N_NODES];
__device__ int2  g_edges[4][N_EDGES];    // (col, val-as-int) sorted by dest row
__device__ int   g_bsum[4][NB_SCAN + 1];
__device__ int   g_bsumx[4][NB_SCAN + 1];

// ---------------------------------------------------------------------------
// GEMM: s0[N,64] = x[N,256] @ W[256,64], fp32.
// ---------------------------------------------------------------------------
__global__ void gemm64(const float* __restrict__ x, const float* __restrict__ W,
                       float* __restrict__ out)
{
    __shared__ float xs[32][64];
    __shared__ float ws[32][64];

    const int tid = threadIdx.x;       // 0..127
    const int tx  = tid & 7;
    const int ty  = tid >> 3;
    const int r0  = blockIdx.x * 64;

    float4 acc0[4] = {};
    float4 acc1[4] = {};

    for (int k0 = 0; k0 < F_IN; k0 += 32) {
        #pragma unroll
        for (int it = 0; it < 4; it++) {
            int li  = it * 128 + tid;
            int row = li >> 3;
            int kq  = li & 7;
            float4 v = make_float4(0.f, 0.f, 0.f, 0.f);
            int gr = r0 + row;
            if (gr < N_NODES)
                v = *(const float4*)(x + (size_t)gr * F_IN + k0 + kq * 4);
            xs[kq * 4 + 0][row] = v.x;
            xs[kq * 4 + 1][row] = v.y;
            xs[kq * 4 + 2][row] = v.z;
            xs[kq * 4 + 3][row] = v.w;
        }
        #pragma unroll
        for (int it = 0; it < 4; it++) {
            int li = it * 128 + tid;
            int kk = li >> 4;
            int cq = li & 15;
            *(float4*)&ws[kk][cq * 4] =
                *(const float4*)(W + (size_t)(k0 + kk) * F_OUT + cq * 4);
        }
        __syncthreads();

        #pragma unroll
        for (int kk = 0; kk < 32; kk++) {
            float4 av = *(const float4*)&xs[kk][ty * 4];
            float4 b0 = *(const float4*)&ws[kk][tx * 4];
            float4 b1 = *(const float4*)&ws[kk][tx * 4 + 32];
            float a4[4] = {av.x, av.y, av.z, av.w};
            #pragma unroll
            for (int j = 0; j < 4; j++) {
                acc0[j].x = fmaf(a4[j], b0.x, acc0[j].x);
                acc0[j].y = fmaf(a4[j], b0.y, acc0[j].y);
                acc0[j].z = fmaf(a4[j], b0.z, acc0[j].z);
                acc0[j].w = fmaf(a4[j], b0.w, acc0[j].w);
                acc1[j].x = fmaf(a4[j], b1.x, acc1[j].x);
                acc1[j].y = fmaf(a4[j], b1.y, acc1[j].y);
                acc1[j].z = fmaf(a4[j], b1.z, acc1[j].z);
                acc1[j].w = fmaf(a4[j], b1.w, acc1[j].w);
            }
        }
        __syncthreads();
    }

    #pragma unroll
    for (int j = 0; j < 4; j++) {
        int gr = r0 + ty * 4 + j;
        if (gr < N_NODES) {
            *(float4*)(out + (size_t)gr * F_OUT + tx * 4)      = acc0[j];
            *(float4*)(out + (size_t)gr * F_OUT + tx * 4 + 32) = acc1[j];
        }
    }
}

// ---------------------------------------------------------------------------
// CSR build: histogram -> exclusive scan (3 kernels) -> scatter
// ---------------------------------------------------------------------------
__global__ void hist_rows(const int* __restrict__ eidx, int* __restrict__ cnt)
{
    int e = blockIdx.x * blockDim.x + threadIdx.x;
    if (e < N_EDGES) atomicAdd(&cnt[eidx[e]], 1);
}

// Block-level exclusive scan: 256 threads x 4 items = 1024 elems per block.
__global__ void scan_blocks(const int* __restrict__ cnt, int* __restrict__ excl,
                            int* __restrict__ bsum)
{
    __shared__ int sh[256];
    const int t = threadIdx.x;
    const int base = blockIdx.x * SCAN_BLK + t * 4;

    int v[4];
    #pragma unroll
    for (int i = 0; i < 4; i++)
        v[i] = (base + i < N_NODES) ? cnt[base + i] : 0;
    int s = v[0] + v[1] + v[2] + v[3];
    sh[t] = s;
    __syncthreads();
    #pragma unroll
    for (int off = 1; off < 256; off <<= 1) {
        int x = (t >= off) ? sh[t - off] : 0;
        __syncthreads();
        sh[t] += x;
        __syncthreads();
    }
    int tbase = sh[t] - s;        // exclusive prefix of this thread's chunk
    int run = tbase;
    #pragma unroll
    for (int i = 0; i < 4; i++) {
        if (base + i < N_NODES) excl[base + i] = run;
        run += v[i];
    }
    if (t == 255) bsum[blockIdx.x] = sh[255];
}

__global__ void scan_bsums(const int* __restrict__ bsum, int* __restrict__ bsumx)
{
    if (threadIdx.x == 0) {
        int s = 0;
        for (int i = 0; i < NB_SCAN; i++) { bsumx[i] = s; s += bsum[i]; }
    }
}

__global__ void scan_addback(const int* __restrict__ bsumx,
                             int* __restrict__ rowptr, int* __restrict__ cursor)
{
    int i = blockIdx.x * blockDim.x + threadIdx.x;
    if (i < N_NODES) {
        int v = rowptr[i] + bsumx[i >> 10];
        rowptr[i] = v;
        cursor[i] = v;
    }
    if (i == N_NODES) rowptr[N_NODES] = N_EDGES;
}

__global__ void scatter_edges(const int* __restrict__ eidx, const float* __restrict__ eval,
                              int* __restrict__ cursor, int2* __restrict__ out)
{
    int e = blockIdx.x * blockDim.x + threadIdx.x;
    if (e < N_EDGES) {
        int   r = eidx[e];
        int   c = eidx[N_EDGES + e];
        float v = eval[e];
        int pos = atomicAdd(&cursor[r], 1);
        out[pos] = make_int2(c, __float_as_int(v));
    }
}

// ---------------------------------------------------------------------------
// CSR SPMM: one warp per destination row, register accumulation, no atomics.
// ---------------------------------------------------------------------------
__global__ void spmm_csr(const int* __restrict__ rowptr, const int2* __restrict__ eg,
                         const float* __restrict__ in, float* __restrict__ out)
{
    const int warp = (blockIdx.x * blockDim.x + threadIdx.x) >> 5;
    const int lane = threadIdx.x & 31;
    if (warp >= N_NODES) return;

    const int s = rowptr[warp];
    const int e = rowptr[warp + 1];
    float ax = 0.f, ay = 0.f;

    for (int b = s; b < e; b += 32) {
        const int m = min(32, e - b);
        int2 ed = make_int2(0, 0);
        if (lane < m) ed = eg[b + lane];

        int j = 0;
        for (; j + 4 <= m; j += 4) {
            int   c0 = __shfl_sync(0xffffffffu, ed.x, j);
            int   c1 = __shfl_sync(0xffffffffu, ed.x, j + 1);
            int   c2 = __shfl_sync(0xffffffffu, ed.x, j + 2);
            int   c3 = __shfl_sync(0xffffffffu, ed.x, j + 3);
            float v0 = __int_as_float(__shfl_sync(0xffffffffu, ed.y, j));
            float v1 = __int_as_float(__shfl_sync(0xffffffffu, ed.y, j + 1));
            float v2 = __int_as_float(__shfl_sync(0xffffffffu, ed.y, j + 2));
            float v3 = __int_as_float(__shfl_sync(0xffffffffu, ed.y, j + 3));
            float2 x0 = *(const float2*)(in + (size_t)c0 * F_OUT + lane * 2);
            float2 x1 = *(const float2*)(in + (size_t)c1 * F_OUT + lane * 2);
            float2 x2 = *(const float2*)(in + (size_t)c2 * F_OUT + lane * 2);
            float2 x3 = *(const float2*)(in + (size_t)c3 * F_OUT + lane * 2);
            ax = fmaf(v0, x0.x, ax); ay = fmaf(v0, x0.y, ay);
            ax = fmaf(v1, x1.x, ax); ay = fmaf(v1, x1.y, ay);
            ax = fmaf(v2, x2.x, ax); ay = fmaf(v2, x2.y, ay);
            ax = fmaf(v3, x3.x, ax); ay = fmaf(v3, x3.y, ay);
        }
        for (; j < m; j++) {
            int   c = __shfl_sync(0xffffffffu, ed.x, j);
            float v = __int_as_float(__shfl_sync(0xffffffffu, ed.y, j));
            float2 xv = *(const float2*)(in + (size_t)c * F_OUT + lane * 2);
            ax = fmaf(v, xv.x, ax); ay = fmaf(v, xv.y, ay);
        }
    }

    float2 r = make_float2(ax, ay);
    *(float2*)(out + (size_t)warp * F_OUT + lane * 2) = r;
}

// ---------------------------------------------------------------------------
// Finalize: e (raw-reshape semantics), softmax, permuted channel-mean h_prime.
// ---------------------------------------------------------------------------
__global__ void finalize(const float* __restrict__ s0, const float* __restrict__ a,
                         float* __restrict__ out_hp, float* __restrict__ out_att)
{
    __shared__ float ch[8][6][64];
    __shared__ float as[768];

    const int tid = threadIdx.x;
    for (int i = tid; i < 768; i += 256) as[i] = a[i];

    const int w    = tid >> 5;
    const int lane = tid & 31;
    const int r    = blockIdx.x * 8 + w;
    __syncthreads();

    #pragma unroll
    for (int c = 0; c < 6; c++) {
        float v0 = g_acc[c][(size_t)r * F_OUT + lane];
        float v1 = g_acc[c][(size_t)r * F_OUT + lane + 32];
        if (c >= 3) { v0 = fabsf(v0); v1 = fabsf(v1); }
        ch[w][c][lane]      = v0;
        ch[w][c][lane + 32] = v1;
    }
    __syncwarp();

    float p[6];
    if (r < N_NODES / 2) {
        size_t b0 = (size_t)(2 * r) * F_OUT;
        size_t b1 = (size_t)(2 * r + 1) * F_OUT;
        float u0 = s0[b0 + lane], u1 = s0[b0 + lane + 32];
        float w0 = s0[b1 + lane], w1 = s0[b1 + lane + 32];
        #pragma unroll
        for (int i = 0; i < 6; i++) {
            const float* ai = as + i * 128;
            p[i] = ai[lane] * u0 + ai[lane + 32] * u1
                 + ai[64 + lane] * w0 + ai[96 + lane] * w1;
        }
    } else {
        int q = 2 * r - N_NODES;
        #pragma unroll
        for (int i = 0; i < 6; i++) {
            float u0 = g_acc[i][(size_t)q * F_OUT + lane];
            float u1 = g_acc[i][(size_t)q * F_OUT + lane + 32];
            float w0 = g_acc[i][(size_t)(q + 1) * F_OUT + lane];
            float w1 = g_acc[i][(size_t)(q + 1) * F_OUT + lane + 32];
            if (i >= 3) { u0 = fabsf(u0); u1 = fabsf(u1); w0 = fabsf(w0); w1 = fabsf(w1); }
            const float* ai = as + i * 128;
            p[i] = ai[lane] * u0 + ai[lane + 32] * u1
                 + ai[64 + lane] * w0 + ai[96 + lane] * w1;
        }
    }

    #pragma unroll
    for (int i = 0; i < 6; i++) {
        #pragma unroll
        for (int off = 16; off; off >>= 1)
            p[i] += __shfl_down_sync(0xffffffffu, p[i], off);
        p[i] = __shfl_sync(0xffffffffu, p[i], 0);
    }

    float m = p[0];
    #pragma unroll
    for (int i = 1; i < 6; i++) m = fmaxf(m, p[i]);
    float att[6], s = 0.f;
    #pragma unroll
    for (int i = 0; i < 6; i++) { att[i] = expf(p[i] - m); s += att[i]; }
    float inv = 1.f / s;
    #pragma unroll
    for (int i = 0; i < 6; i++) att[i] *= inv;

    if (out_att && lane == 0) {
        #pragma unroll
        for (int i = 0; i < 6; i++) out_att[(size_t)r * 6 + i] = att[i];
    }

    #pragma unroll
    for (int kk = 0; kk < 2; kk++) {
        int k = lane + kk * 32;
        float hp = 0.f;
        #pragma unroll
        for (int j = 0; j < 6; j++) {
            int idx = j * 64 + k;
            hp = fmaf(att[j], ch[w][idx % 6][idx / 6], hp);
        }
        out_hp[(size_t)r * F_OUT + k] = hp * (1.0f / 6.0f);
    }
}

// ---------------------------------------------------------------------------
extern "C" void kernel_launch(void* const* d_in, const int* in_sizes, int n_in,
                              void* d_out, int out_size)
{
    const float* x      = (const float*)d_in[0];
    const float* W      = (const float*)d_in[1];
    const float* a      = (const float*)d_in[2];
    const int*   idx4[4]  = { (const int*)d_in[3], (const int*)d_in[5],
                              (const int*)d_in[7], (const int*)d_in[9] };
    const float* val4[4]  = { (const float*)d_in[4], (const float*)d_in[6],
                              (const float*)d_in[8], (const float*)d_in[10] };

    float* s0;   cudaGetSymbolAddress((void**)&s0,  g_s0);
    float* acc;  cudaGetSymbolAddress((void**)&acc, g_acc);
    int*   cnt;  cudaGetSymbolAddress((void**)&cnt, g_cnt);
    int*   rp;   cudaGetSymbolAddress((void**)&rp,  g_rowptr);
    int*   cur;  cudaGetSymbolAddress((void**)&cur, g_cursor);
    int2*  eg;   cudaGetSymbolAddress((void**)&eg,  g_edges);
    int*   bs;   cudaGetSymbolAddress((void**)&bs,  g_bsum);
    int*   bsx;  cudaGetSymbolAddress((void**)&bsx, g_bsumx);

    // GEMM first (independent of CSR build)
    gemm64<<<(N_NODES + 63) / 64, 128>>>(x, W, s0);

    // CSR build for the 4 operators
    cudaMemsetAsync(cnt, 0, sizeof(int) * 4 * N_NODES, 0);
    const int EG = (N_EDGES + 255) / 256;
    for (int o = 0; o < 4; o++)
        hist_rows<<<EG, 256>>>(idx4[o], cnt + o * N_NODES);
    for (int o = 0; o < 4; o++)
        scan_blocks<<<NB_SCAN, 256>>>(cnt + o * N_NODES,
                                      rp + o * (N_NODES + 1),
                                      bs + o * (NB_SCAN + 1));
    for (int o = 0; o < 4; o++)
        scan_bsums<<<1, 32>>>(bs + o * (NB_SCAN + 1), bsx + o * (NB_SCAN + 1));
    for (int o = 0; o < 4; o++)
        scan_addback<<<(N_NODES + 256) / 256, 256>>>(bsx + o * (NB_SCAN + 1),
                                                     rp + o * (N_NODES + 1),
                                                     cur + o * N_NODES);
    for (int o = 0; o < 4; o++)
        scatter_edges<<<EG, 256>>>(idx4[o], val4[o], cur + o * N_NODES,
                                   eg + (size_t)o * N_EDGES);

    // 6 SPMMs (A chained 3x, then P1..P3)
    const int SG = (N_NODES * 32 + 255) / 256;
    spmm_csr<<<SG, 256>>>(rp, eg, s0, acc + 0 * (size_t)NF);
    spmm_csr<<<SG, 256>>>(rp, eg, acc + 0 * (size_t)NF, acc + 1 * (size_t)NF);
    spmm_csr<<<SG, 256>>>(rp, eg, acc + 1 * (size_t)NF, acc + 2 * (size_t)NF);
    spmm_csr<<<SG, 256>>>(rp + 1 * (N_NODES + 1), eg + 1 * (size_t)N_EDGES, s0, acc + 3 * (size_t)NF);
    spmm_csr<<<SG, 256>>>(rp + 2 * (N_NODES + 1), eg + 2 * (size_t)N_EDGES, s0, acc + 4 * (size_t)NF);
    spmm_csr<<<SG, 256>>>(rp + 3 * (N_NODES + 1), eg + 3 * (size_t)N_EDGES, s0, acc + 5 * (size_t)NF);

    float* out = (float*)d_out;
    float* att = (out_size >= N_NODES * F_OUT + N_NODES * 6)
                     ? out + (size_t)N_NODES * F_OUT : nullptr;
    finalize<<<N_NODES / 8, 256>>>(s0, a, out, att);
}

// round 3
// speedup vs baseline: 1.1792x; 1.0276x over previous
#include <cuda_runtime.h>
#include <cuda_bf16.h>
#include <cstddef>

#define N_NODES 100000
#define N_EDGES 3200000
#define F_IN    256
#define F_OUT   64
#define NF      (N_NODES * F_OUT)
#define SCAN_BLK 1024
#define NB_SCAN  ((N_NODES + SCAN_BLK - 1) / SCAN_BLK)   // 98

// Scratch (device globals; allocation-free).
__device__ float g_s0[NF];
__device__ float g_acc[6][NF];           // hA, hA2, hA3, hs1, hs2, hs3
__device__ int   g_cnt[4][N_NODES];      // per-op row histograms
__device__ int   g_rowptr[4][N_NODES + 1];
__device__ int   g_rank[4][N_EDGES];     // intra-row rank per edge
__device__ int2  g_edges[4][N_EDGES];    // (col, val-as-int) sorted by dest row
__device__ int   g_bsum[4][NB_SCAN + 1];
__device__ int   g_bsumx[4][NB_SCAN + 1];

// ---------------------------------------------------------------------------
// GEMM: s0[N,64] = x[N,256] @ W[256,64], fp32.
// ---------------------------------------------------------------------------
__global__ void gemm64(const float* __restrict__ x, const float* __restrict__ W,
                       float* __restrict__ out)
{
    __shared__ float xs[32][64];
    __shared__ float ws[32][64];

    const int tid = threadIdx.x;       // 0..127
    const int tx  = tid & 7;
    const int ty  = tid >> 3;
    const int r0  = blockIdx.x * 64;

    float4 acc0[4] = {};
    float4 acc1[4] = {};

    for (int k0 = 0; k0 < F_IN; k0 += 32) {
        #pragma unroll
        for (int it = 0; it < 4; it++) {
            int li  = it * 128 + tid;
            int row = li >> 3;
            int kq  = li & 7;
            float4 v = make_float4(0.f, 0.f, 0.f, 0.f);
            int gr = r0 + row;
            if (gr < N_NODES)
                v = *(const float4*)(x + (size_t)gr * F_IN + k0 + kq * 4);
            xs[kq * 4 + 0][row] = v.x;
            xs[kq * 4 + 1][row] = v.y;
            xs[kq * 4 + 2][row] = v.z;
            xs[kq * 4 + 3][row] = v.w;
        }
        #pragma unroll
        for (int it = 0; it < 4; it++) {
            int li = it * 128 + tid;
            int kk = li >> 4;
            int cq = li & 15;
            *(float4*)&ws[kk][cq * 4] =
                *(const float4*)(W + (size_t)(k0 + kk) * F_OUT + cq * 4);
        }
        __syncthreads();

        #pragma unroll
        for (int kk = 0; kk < 32; kk++) {
            float4 av = *(const float4*)&xs[kk][ty * 4];
            float4 b0 = *(const float4*)&ws[kk][tx * 4];
            float4 b1 = *(const float4*)&ws[kk][tx * 4 + 32];
            float a4[4] = {av.x, av.y, av.z, av.w};
            #pragma unroll
            for (int j = 0; j < 4; j++) {
                acc0[j].x = fmaf(a4[j], b0.x, acc0[j].x);
                acc0[j].y = fmaf(a4[j], b0.y, acc0[j].y);
                acc0[j].z = fmaf(a4[j], b0.z, acc0[j].z);
                acc0[j].w = fmaf(a4[j], b0.w, acc0[j].w);
                acc1[j].x = fmaf(a4[j], b1.x, acc1[j].x);
                acc1[j].y = fmaf(a4[j], b1.y, acc1[j].y);
                acc1[j].z = fmaf(a4[j], b1.z, acc1[j].z);
                acc1[j].w = fmaf(a4[j], b1.w, acc1[j].w);
            }
        }
        __syncthreads();
    }

    #pragma unroll
    for (int j = 0; j < 4; j++) {
        int gr = r0 + ty * 4 + j;
        if (gr < N_NODES) {
            *(float4*)(out + (size_t)gr * F_OUT + tx * 4)      = acc0[j];
            *(float4*)(out + (size_t)gr * F_OUT + tx * 4 + 32) = acc1[j];
        }
    }
}

// ---------------------------------------------------------------------------
// CSR build (fused across 4 operators via blockIdx.y):
//   hist_rank -> scan_blocks -> scan_bsums (warp scans) -> addback -> scatter
// ---------------------------------------------------------------------------
__global__ void hist_rank(const int* __restrict__ i0, const int* __restrict__ i1,
                          const int* __restrict__ i2, const int* __restrict__ i3,
                          int* __restrict__ cnt, int* __restrict__ rank)
{
    const int op = blockIdx.y;
    const int* idx = (op == 0) ? i0 : (op == 1) ? i1 : (op == 2) ? i2 : i3;
    int e = blockIdx.x * blockDim.x + threadIdx.x;
    if (e < N_EDGES) {
        int r = idx[e];
        rank[(size_t)op * N_EDGES + e] = atomicAdd(&cnt[op * N_NODES + r], 1);
    }
}

// Block-level exclusive scan: 256 threads x 4 items = 1024 elems per block.
__global__ void scan_blocks(const int* __restrict__ cnt, int* __restrict__ excl,
                            int* __restrict__ bsum)
{
    __shared__ int sh[256];
    const int op = blockIdx.y;
    const int t = threadIdx.x;
    const int base = blockIdx.x * SCAN_BLK + t * 4;
    const int* c = cnt + op * N_NODES;
    int* ex = excl + op * (N_NODES + 1);

    int v[4];
    #pragma unroll
    for (int i = 0; i < 4; i++)
        v[i] = (base + i < N_NODES) ? c[base + i] : 0;
    int s = v[0] + v[1] + v[2] + v[3];
    sh[t] = s;
    __syncthreads();
    #pragma unroll
    for (int off = 1; off < 256; off <<= 1) {
        int x = (t >= off) ? sh[t - off] : 0;
        __syncthreads();
        sh[t] += x;
        __syncthreads();
    }
    int run = sh[t] - s;
    #pragma unroll
    for (int i = 0; i < 4; i++) {
        if (base + i < N_NODES) ex[base + i] = run;
        run += v[i];
    }
    if (t == 255) bsum[op * (NB_SCAN + 1) + blockIdx.x] = sh[255];
}

// One block, 4 warps: warp w scans op w's 98 block sums (shfl inclusive scan).
__global__ void scan_bsums(const int* __restrict__ bsum, int* __restrict__ bsumx)
{
    const int op   = threadIdx.x >> 5;
    const int lane = threadIdx.x & 31;
    const int* b = bsum  + op * (NB_SCAN + 1);
    int*      bx = bsumx + op * (NB_SCAN + 1);
    int carry = 0;
    #pragma unroll
    for (int c = 0; c < (NB_SCAN + 31) / 32; c++) {
        int i = c * 32 + lane;
        int v = (i < NB_SCAN) ? b[i] : 0;
        int s = v;
        #pragma unroll
        for (int off = 1; off < 32; off <<= 1) {
            int t = __shfl_up_sync(0xffffffffu, s, off);
            if (lane >= off) s += t;
        }
        if (i < NB_SCAN) bx[i] = carry + s - v;   // exclusive
        carry += __shfl_sync(0xffffffffu, s, 31);
    }
}

__global__ void scan_addback(const int* __restrict__ bsumx, int* __restrict__ rowptr)
{
    const int op = blockIdx.y;
    int i = blockIdx.x * blockDim.x + threadIdx.x;
    int* rp = rowptr + op * (N_NODES + 1);
    if (i < N_NODES)
        rp[i] += bsumx[op * (NB_SCAN + 1) + (i >> 10)];
    if (i == N_NODES) rp[N_NODES] = N_EDGES;
}

__global__ void scatter_edges(const int* __restrict__ i0, const int* __restrict__ i1,
                              const int* __restrict__ i2, const int* __restrict__ i3,
                              const float* __restrict__ v0, const float* __restrict__ v1,
                              const float* __restrict__ v2, const float* __restrict__ v3,
                              const int* __restrict__ rowptr, const int* __restrict__ rank,
                              int2* __restrict__ out)
{
    const int op = blockIdx.y;
    const int*   idx = (op == 0) ? i0 : (op == 1) ? i1 : (op == 2) ? i2 : i3;
    const float* val = (op == 0) ? v0 : (op == 1) ? v1 : (op == 2) ? v2 : v3;
    int e = blockIdx.x * blockDim.x + threadIdx.x;
    if (e < N_EDGES) {
        int   r = idx[e];
        int   c = idx[N_EDGES + e];
        float v = val[e];
        int pos = rowptr[op * (N_NODES + 1) + r] + rank[(size_t)op * N_EDGES + e];
        out[(size_t)op * N_EDGES + pos] = make_int2(c, __float_as_int(v));
    }
}

// ---------------------------------------------------------------------------
// CSR SPMM: one warp per destination row, register accumulation, no atomics.
// ---------------------------------------------------------------------------
__global__ void spmm_csr(const int* __restrict__ rowptr, const int2* __restrict__ eg,
                         const float* __restrict__ in, float* __restrict__ out)
{
    const int warp = (blockIdx.x * blockDim.x + threadIdx.x) >> 5;
    const int lane = threadIdx.x & 31;
    if (warp >= N_NODES) return;

    const int s = rowptr[warp];
    const int e = rowptr[warp + 1];
    float ax = 0.f, ay = 0.f;

    for (int b = s; b < e; b += 32) {
        const int m = min(32, e - b);
        int2 ed = make_int2(0, 0);
        if (lane < m) ed = eg[b + lane];

        int j = 0;
        for (; j + 4 <= m; j += 4) {
            int   c0 = __shfl_sync(0xffffffffu, ed.x, j);
            int   c1 = __shfl_sync(0xffffffffu, ed.x, j + 1);
            int   c2 = __shfl_sync(0xffffffffu, ed.x, j + 2);
            int   c3 = __shfl_sync(0xffffffffu, ed.x, j + 3);
            float v0 = __int_as_float(__shfl_sync(0xffffffffu, ed.y, j));
            float v1 = __int_as_float(__shfl_sync(0xffffffffu, ed.y, j + 1));
            float v2 = __int_as_float(__shfl_sync(0xffffffffu, ed.y, j + 2));
            float v3 = __int_as_float(__shfl_sync(0xffffffffu, ed.y, j + 3));
            float2 x0 = *(const float2*)(in + (size_t)c0 * F_OUT + lane * 2);
            float2 x1 = *(const float2*)(in + (size_t)c1 * F_OUT + lane * 2);
            float2 x2 = *(const float2*)(in + (size_t)c2 * F_OUT + lane * 2);
            float2 x3 = *(const float2*)(in + (size_t)c3 * F_OUT + lane * 2);
            ax = fmaf(v0, x0.x, ax); ay = fmaf(v0, x0.y, ay);
            ax = fmaf(v1, x1.x, ax); ay = fmaf(v1, x1.y, ay);
            ax = fmaf(v2, x2.x, ax); ay = fmaf(v2, x2.y, ay);
            ax = fmaf(v3, x3.x, ax); ay = fmaf(v3, x3.y, ay);
        }
        for (; j < m; j++) {
            int   c = __shfl_sync(0xffffffffu, ed.x, j);
            float v = __int_as_float(__shfl_sync(0xffffffffu, ed.y, j));
            float2 xv = *(const float2*)(in + (size_t)c * F_OUT + lane * 2);
            ax = fmaf(v, xv.x, ax); ay = fmaf(v, xv.y, ay);
        }
    }

    *(float2*)(out + (size_t)warp * F_OUT + lane * 2) = make_float2(ax, ay);
}

// ---------------------------------------------------------------------------
// Finalize: e (raw-reshape semantics), softmax, permuted channel-mean h_prime.
// ---------------------------------------------------------------------------
__global__ void finalize(const float* __restrict__ s0, const float* __restrict__ a,
                         float* __restrict__ out_hp, float* __restrict__ out_att)
{
    __shared__ float ch[8][6][64];
    __shared__ float as[768];

    const int tid = threadIdx.x;
    for (int i = tid; i < 768; i += 256) as[i] = a[i];

    const int w    = tid >> 5;
    const int lane = tid & 31;
    const int r    = blockIdx.x * 8 + w;
    __syncthreads();

    #pragma unroll
    for (int c = 0; c < 6; c++) {
        float v0 = g_acc[c][(size_t)r * F_OUT + lane];
        float v1 = g_acc[c][(size_t)r * F_OUT + lane + 32];
        if (c >= 3) { v0 = fabsf(v0); v1 = fabsf(v1); }
        ch[w][c][lane]      = v0;
        ch[w][c][lane + 32] = v1;
    }
    __syncwarp();

    float p[6];
    if (r < N_NODES / 2) {
        size_t b0 = (size_t)(2 * r) * F_OUT;
        size_t b1 = (size_t)(2 * r + 1) * F_OUT;
        float u0 = s0[b0 + lane], u1 = s0[b0 + lane + 32];
        float w0 = s0[b1 + lane], w1 = s0[b1 + lane + 32];
        #pragma unroll
        for (int i = 0; i < 6; i++) {
            const float* ai = as + i * 128;
            p[i] = ai[lane] * u0 + ai[lane + 32] * u1
                 + ai[64 + lane] * w0 + ai[96 + lane] * w1;
        }
    } else {
        int q = 2 * r - N_NODES;
        #pragma unroll
        for (int i = 0; i < 6; i++) {
            float u0 = g_acc[i][(size_t)q * F_OUT + lane];
            float u1 = g_acc[i][(size_t)q * F_OUT + lane + 32];
            float w0 = g_acc[i][(size_t)(q + 1) * F_OUT + lane];
            float w1 = g_acc[i][(size_t)(q + 1) * F_OUT + lane + 32];
            if (i >= 3) { u0 = fabsf(u0); u1 = fabsf(u1); w0 = fabsf(w0); w1 = fabsf(w1); }
            const float* ai = as + i * 128;
            p[i] = ai[lane] * u0 + ai[lane + 32] * u1
                 + ai[64 + lane] * w0 + ai[96 + lane] * w1;
        }
    }

    #pragma unroll
    for (int i = 0; i < 6; i++) {
        #pragma unroll
        for (int off = 16; off; off >>= 1)
            p[i] += __shfl_down_sync(0xffffffffu, p[i], off);
        p[i] = __shfl_sync(0xffffffffu, p[i], 0);
    }

    float m = p[0];
    #pragma unroll
    for (int i = 1; i < 6; i++) m = fmaxf(m, p[i]);
    float att[6], s = 0.f;
    #pragma unroll
    for (int i = 0; i < 6; i++) { att[i] = expf(p[i] - m); s += att[i]; }
    float inv = 1.f / s;
    #pragma unroll
    for (int i = 0; i < 6; i++) att[i] *= inv;

    if (out_att && lane == 0) {
        #pragma unroll
        for (int i = 0; i < 6; i++) out_att[(size_t)r * 6 + i] = att[i];
    }

    #pragma unroll
    for (int kk = 0; kk < 2; kk++) {
        int k = lane + kk * 32;
        float hp = 0.f;
        #pragma unroll
        for (int j = 0; j < 6; j++) {
            int idx = j * 64 + k;
            hp = fmaf(att[j], ch[w][idx % 6][idx / 6], hp);
        }
        out_hp[(size_t)r * F_OUT + k] = hp * (1.0f / 6.0f);
    }
}

// ---------------------------------------------------------------------------
extern "C" void kernel_launch(void* const* d_in, const int* in_sizes, int n_in,
                              void* d_out, int out_size)
{
    const float* x  = (const float*)d_in[0];
    const float* W  = (const float*)d_in[1];
    const float* a  = (const float*)d_in[2];
    const int*   iA  = (const int*)d_in[3];   const float* vA  = (const float*)d_in[4];
    const int*   iP1 = (const int*)d_in[5];   const float* vP1 = (const float*)d_in[6];
    const int*   iP2 = (const int*)d_in[7];   const float* vP2 = (const float*)d_in[8];
    const int*   iP3 = (const int*)d_in[9];   const float* vP3 = (const float*)d_in[10];

    float* s0;   cudaGetSymbolAddress((void**)&s0,  g_s0);
    float* acc;  cudaGetSymbolAddress((void**)&acc, g_acc);
    int*   cnt;  cudaGetSymbolAddress((void**)&cnt, g_cnt);
    int*   rp;   cudaGetSymbolAddress((void**)&rp,  g_rowptr);
    int*   rk;   cudaGetSymbolAddress((void**)&rk,  g_rank);
    int2*  eg;   cudaGetSymbolAddress((void**)&eg,  g_edges);
    int*   bs;   cudaGetSymbolAddress((void**)&bs,  g_bsum);
    int*   bsx;  cudaGetSymbolAddress((void**)&bsx, g_bsumx);

    // GEMM first (independent of CSR build)
    gemm64<<<(N_NODES + 63) / 64, 128>>>(x, W, s0);

    // Fused CSR build for all 4 operators
    cudaMemsetAsync(cnt, 0, sizeof(int) * 4 * N_NODES, 0);
    const dim3 EG((N_EDGES + 255) / 256, 4);
    hist_rank<<<EG, 256>>>(iA, iP1, iP2, iP3, cnt, rk);
    scan_blocks<<<dim3(NB_SCAN, 4), 256>>>(cnt, rp, bs);
    scan_bsums<<<1, 128>>>(bs, bsx);
    scan_addback<<<dim3((N_NODES + 256) / 256, 4), 256>>>(bsx, rp);
    scatter_edges<<<EG, 256>>>(iA, iP1, iP2, iP3, vA, vP1, vP2, vP3, rp, rk, eg);

    // 6 SPMMs (A chained 3x, then P1..P3)
    const int SG = (N_NODES * 32 + 255) / 256;
    spmm_csr<<<SG, 256>>>(rp, eg, s0, acc + 0 * (size_t)NF);
    spmm_csr<<<SG, 256>>>(rp, eg, acc + 0 * (size_t)NF, acc + 1 * (size_t)NF);
    spmm_csr<<<SG, 256>>>(rp, eg, acc + 1 * (size_t)NF, acc + 2 * (size_t)NF);
    spmm_csr<<<SG, 256>>>(rp + 1 * (N_NODES + 1), eg + 1 * (size_t)N_EDGES, s0, acc + 3 * (size_t)NF);
    spmm_csr<<<SG, 256>>>(rp + 2 * (N_NODES + 1), eg + 2 * (size_t)N_EDGES, s0, acc + 4 * (size_t)NF);
    spmm_csr<<<SG, 256>>>(rp + 3 * (N_NODES + 1), eg + 3 * (size_t)N_EDGES, s0, acc + 5 * (size_t)NF);

    float* out = (float*)d_out;
    float* att = (out_size >= N_NODES * F_OUT + N_NODES * 6)
                     ? out + (size_t)N_NODES * F_OUT : nullptr;
    finalize<<<N_NODES / 8, 256>>>(s0, a, out, att);
}

// round 4
// speedup vs baseline: 1.2541x; 1.0635x over previous
#include <cuda_runtime.h>
#include <cuda_fp16.h>
#include <cstddef>

#define N_NODES 100000
#define N_EDGES 3200000
#define F_IN    256
#define F_OUT   64
#define NF      (N_NODES * F_OUT)
#define SCAN_BLK 1024
#define NB_SCAN  ((N_NODES + SCAN_BLK - 1) / SCAN_BLK)   // 98

// Scratch (device globals; allocation-free).
__device__ float  g_s0[NF];
__device__ __half g_s0h[NF];             // fp16 copy of s0 for P-channel gathers
__device__ float  g_acc[6][NF];          // hA, hA2, hA3, hs1, hs2, hs3
__device__ int    g_cnt[4][N_NODES];
__device__ int    g_rowptr[4][N_NODES + 1];
__device__ int    g_rank[4][N_EDGES];
__device__ int2   g_edges[4][N_EDGES];
__device__ int    g_bsum[4][NB_SCAN + 1];
__device__ int    g_bsumx[4][NB_SCAN + 1];

// ---------------------------------------------------------------------------
// GEMM: s0[N,64] = x[N,256] @ W[256,64], fp32; also emits fp16 copy.
// ---------------------------------------------------------------------------
__global__ void gemm64(const float* __restrict__ x, const float* __restrict__ W,
                       float* __restrict__ out, __half* __restrict__ outh)
{
    __shared__ float xs[32][64];
    __shared__ float ws[32][64];

    const int tid = threadIdx.x;       // 0..127
    const int tx  = tid & 7;
    const int ty  = tid >> 3;
    const int r0  = blockIdx.x * 64;

    float4 acc0[4] = {};
    float4 acc1[4] = {};

    for (int k0 = 0; k0 < F_IN; k0 += 32) {
        #pragma unroll
        for (int it = 0; it < 4; it++) {
            int li  = it * 128 + tid;
            int row = li >> 3;
            int kq  = li & 7;
            float4 v = make_float4(0.f, 0.f, 0.f, 0.f);
            int gr = r0 + row;
            if (gr < N_NODES)
                v = *(const float4*)(x + (size_t)gr * F_IN + k0 + kq * 4);
            xs[kq * 4 + 0][row] = v.x;
            xs[kq * 4 + 1][row] = v.y;
            xs[kq * 4 + 2][row] = v.z;
            xs[kq * 4 + 3][row] = v.w;
        }
        #pragma unroll
        for (int it = 0; it < 4; it++) {
            int li = it * 128 + tid;
            int kk = li >> 4;
            int cq = li & 15;
            *(float4*)&ws[kk][cq * 4] =
                *(const float4*)(W + (size_t)(k0 + kk) * F_OUT + cq * 4);
        }
        __syncthreads();

        #pragma unroll
        for (int kk = 0; kk < 32; kk++) {
            float4 av = *(const float4*)&xs[kk][ty * 4];
            float4 b0 = *(const float4*)&ws[kk][tx * 4];
            float4 b1 = *(const float4*)&ws[kk][tx * 4 + 32];
            float a4[4] = {av.x, av.y, av.z, av.w};
            #pragma unroll
            for (int j = 0; j < 4; j++) {
                acc0[j].x = fmaf(a4[j], b0.x, acc0[j].x);
                acc0[j].y = fmaf(a4[j], b0.y, acc0[j].y);
                acc0[j].z = fmaf(a4[j], b0.z, acc0[j].z);
                acc0[j].w = fmaf(a4[j], b0.w, acc0[j].w);
                acc1[j].x = fmaf(a4[j], b1.x, acc1[j].x);
                acc1[j].y = fmaf(a4[j], b1.y, acc1[j].y);
                acc1[j].z = fmaf(a4[j], b1.z, acc1[j].z);
                acc1[j].w = fmaf(a4[j], b1.w, acc1[j].w);
            }
        }
        __syncthreads();
    }

    #pragma unroll
    for (int j = 0; j < 4; j++) {
        int gr = r0 + ty * 4 + j;
        if (gr < N_NODES) {
            *(float4*)(out + (size_t)gr * F_OUT + tx * 4)      = acc0[j];
            *(float4*)(out + (size_t)gr * F_OUT + tx * 4 + 32) = acc1[j];
            __half2* hp = (__half2*)(outh + (size_t)gr * F_OUT);
            hp[tx * 2]      = __floats2half2_rn(acc0[j].x, acc0[j].y);
            hp[tx * 2 + 1]  = __floats2half2_rn(acc0[j].z, acc0[j].w);
            hp[tx * 2 + 16] = __floats2half2_rn(acc1[j].x, acc1[j].y);
            hp[tx * 2 + 17] = __floats2half2_rn(acc1[j].z, acc1[j].w);
        }
    }
}

// ---------------------------------------------------------------------------
// CSR build (fused across 4 operators via blockIdx.y)
// ---------------------------------------------------------------------------
__global__ void hist_rank(const int* __restrict__ i0, const int* __restrict__ i1,
                          const int* __restrict__ i2, const int* __restrict__ i3,
                          int* __restrict__ cnt, int* __restrict__ rank)
{
    const int op = blockIdx.y;
    const int* idx = (op == 0) ? i0 : (op == 1) ? i1 : (op == 2) ? i2 : i3;
    int e = blockIdx.x * blockDim.x + threadIdx.x;
    if (e < N_EDGES) {
        int r = idx[e];
        rank[(size_t)op * N_EDGES + e] = atomicAdd(&cnt[op * N_NODES + r], 1);
    }
}

__global__ void scan_blocks(const int* __restrict__ cnt, int* __restrict__ excl,
                            int* __restrict__ bsum)
{
    __shared__ int sh[256];
    const int op = blockIdx.y;
    const int t = threadIdx.x;
    const int base = blockIdx.x * SCAN_BLK + t * 4;
    const int* c = cnt + op * N_NODES;
    int* ex = excl + op * (N_NODES + 1);

    int v[4];
    #pragma unroll
    for (int i = 0; i < 4; i++)
        v[i] = (base + i < N_NODES) ? c[base + i] : 0;
    int s = v[0] + v[1] + v[2] + v[3];
    sh[t] = s;
    __syncthreads();
    #pragma unroll
    for (int off = 1; off < 256; off <<= 1) {
        int x = (t >= off) ? sh[t - off] : 0;
        __syncthreads();
        sh[t] += x;
        __syncthreads();
    }
    int run = sh[t] - s;
    #pragma unroll
    for (int i = 0; i < 4; i++) {
        if (base + i < N_NODES) ex[base + i] = run;
        run += v[i];
    }
    if (t == 255) bsum[op * (NB_SCAN + 1) + blockIdx.x] = sh[255];
}

__global__ void scan_bsums(const int* __restrict__ bsum, int* __restrict__ bsumx)
{
    const int op   = threadIdx.x >> 5;
    const int lane = threadIdx.x & 31;
    const int* b = bsum  + op * (NB_SCAN + 1);
    int*      bx = bsumx + op * (NB_SCAN + 1);
    int carry = 0;
    #pragma unroll
    for (int c = 0; c < (NB_SCAN + 31) / 32; c++) {
        int i = c * 32 + lane;
        int v = (i < NB_SCAN) ? b[i] : 0;
        int s = v;
        #pragma unroll
        for (int off = 1; off < 32; off <<= 1) {
            int t = __shfl_up_sync(0xffffffffu, s, off);
            if (lane >= off) s += t;
        }
        if (i < NB_SCAN) bx[i] = carry + s - v;
        carry += __shfl_sync(0xffffffffu, s, 31);
    }
}

__global__ void scan_addback(const int* __restrict__ bsumx, int* __restrict__ rowptr)
{
    const int op = blockIdx.y;
    int i = blockIdx.x * blockDim.x + threadIdx.x;
    int* rp = rowptr + op * (N_NODES + 1);
    if (i < N_NODES)
        rp[i] += bsumx[op * (NB_SCAN + 1) + (i >> 10)];
    if (i == N_NODES) rp[N_NODES] = N_EDGES;
}

__global__ void scatter_edges(const int* __restrict__ i0, const int* __restrict__ i1,
                              const int* __restrict__ i2, const int* __restrict__ i3,
                              const float* __restrict__ v0, const float* __restrict__ v1,
                              const float* __restrict__ v2, const float* __restrict__ v3,
                              const int* __restrict__ rowptr, const int* __restrict__ rank,
                              int2* __restrict__ out)
{
    const int op = blockIdx.y;
    const int*   idx = (op == 0) ? i0 : (op == 1) ? i1 : (op == 2) ? i2 : i3;
    const float* val = (op == 0) ? v0 : (op == 1) ? v1 : (op == 2) ? v2 : v3;
    int e = blockIdx.x * blockDim.x + threadIdx.x;
    if (e < N_EDGES) {
        int   r = idx[e];
        int   c = idx[N_EDGES + e];
        float v = val[e];
        int pos = rowptr[op * (N_NODES + 1) + r] + rank[(size_t)op * N_EDGES + e];
        out[(size_t)op * N_EDGES + pos] = make_int2(c, __float_as_int(v));
    }
}

// ---------------------------------------------------------------------------
// CSR SPMM, fp32 gather: one warp per destination row.
// ---------------------------------------------------------------------------
__global__ void spmm_csr(const int* __restrict__ rowptr, const int2* __restrict__ eg,
                         const float* __restrict__ in, float* __restrict__ out)
{
    const int warp = (blockIdx.x * blockDim.x + threadIdx.x) >> 5;
    const int lane = threadIdx.x & 31;
    if (warp >= N_NODES) return;

    const int s = rowptr[warp];
    const int e = rowptr[warp + 1];
    float ax = 0.f, ay = 0.f;

    for (int b = s; b < e; b += 32) {
        const int m = min(32, e - b);
        int2 ed = make_int2(0, 0);
        if (lane < m) ed = eg[b + lane];

        int j = 0;
        for (; j + 4 <= m; j += 4) {
            int   c0 = __shfl_sync(0xffffffffu, ed.x, j);
            int   c1 = __shfl_sync(0xffffffffu, ed.x, j + 1);
            int   c2 = __shfl_sync(0xffffffffu, ed.x, j + 2);
            int   c3 = __shfl_sync(0xffffffffu, ed.x, j + 3);
            float v0 = __int_as_float(__shfl_sync(0xffffffffu, ed.y, j));
            float v1 = __int_as_float(__shfl_sync(0xffffffffu, ed.y, j + 1));
            float v2 = __int_as_float(__shfl_sync(0xffffffffu, ed.y, j + 2));
            float v3 = __int_as_float(__shfl_sync(0xffffffffu, ed.y, j + 3));
            float2 x0 = *(const float2*)(in + (size_t)c0 * F_OUT + lane * 2);
            float2 x1 = *(const float2*)(in + (size_t)c1 * F_OUT + lane * 2);
            float2 x2 = *(const float2*)(in + (size_t)c2 * F_OUT + lane * 2);
            float2 x3 = *(const float2*)(in + (size_t)c3 * F_OUT + lane * 2);
            ax = fmaf(v0, x0.x, ax); ay = fmaf(v0, x0.y, ay);
            ax = fmaf(v1, x1.x, ax); ay = fmaf(v1, x1.y, ay);
            ax = fmaf(v2, x2.x, ax); ay = fmaf(v2, x2.y, ay);
            ax = fmaf(v3, x3.x, ax); ay = fmaf(v3, x3.y, ay);
        }
        for (; j < m; j++) {
            int   c = __shfl_sync(0xffffffffu, ed.x, j);
            float v = __int_as_float(__shfl_sync(0xffffffffu, ed.y, j));
            float2 xv = *(const float2*)(in + (size_t)c * F_OUT + lane * 2);
            ax = fmaf(v, xv.x, ax); ay = fmaf(v, xv.y, ay);
        }
    }

    *(float2*)(out + (size_t)warp * F_OUT + lane * 2) = make_float2(ax, ay);
}

// ---------------------------------------------------------------------------
// CSR SPMM, fp16 gather source, fp32 accumulate. gridDim.y = 3 (P1..P3).
// ---------------------------------------------------------------------------
__global__ void spmm_csr_h3(const int* __restrict__ rowptr_all,
                            const int2* __restrict__ eg_all,
                            const __half* __restrict__ in,
                            float* __restrict__ acc_all)
{
    const int op = blockIdx.y;                          // 0..2 -> operators 1..3
    const int* rowptr = rowptr_all + (op + 1) * (N_NODES + 1);
    const int2* eg    = eg_all + (size_t)(op + 1) * N_EDGES;
    float* out        = acc_all + (size_t)(op + 3) * NF;

    const int warp = (blockIdx.x * blockDim.x + threadIdx.x) >> 5;
    const int lane = threadIdx.x & 31;
    if (warp >= N_NODES) return;

    const int s = rowptr[warp];
    const int e = rowptr[warp + 1];
    float ax = 0.f, ay = 0.f;

    for (int b = s; b < e; b += 32) {
        const int m = min(32, e - b);
        int2 ed = make_int2(0, 0);
        if (lane < m) ed = eg[b + lane];

        int j = 0;
        for (; j + 4 <= m; j += 4) {
            int   c0 = __shfl_sync(0xffffffffu, ed.x, j);
            int   c1 = __shfl_sync(0xffffffffu, ed.x, j + 1);
            int   c2 = __shfl_sync(0xffffffffu, ed.x, j + 2);
            int   c3 = __shfl_sync(0xffffffffu, ed.x, j + 3);
            float v0 = __int_as_float(__shfl_sync(0xffffffffu, ed.y, j));
            float v1 = __int_as_float(__shfl_sync(0xffffffffu, ed.y, j + 1));
            float v2 = __int_as_float(__shfl_sync(0xffffffffu, ed.y, j + 2));
            float v3 = __int_as_float(__shfl_sync(0xffffffffu, ed.y, j + 3));
            float2 x0 = __half22float2(*((const __half2*)(in + (size_t)c0 * F_OUT) + lane));
            float2 x1 = __half22float2(*((const __half2*)(in + (size_t)c1 * F_OUT) + lane));
            float2 x2 = __half22float2(*((const __half2*)(in + (size_t)c2 * F_OUT) + lane));
            float2 x3 = __half22float2(*((const __half2*)(in + (size_t)c3 * F_OUT) + lane));
            ax = fmaf(v0, x0.x, ax); ay = fmaf(v0, x0.y, ay);
            ax = fmaf(v1, x1.x, ax); ay = fmaf(v1, x1.y, ay);
            ax = fmaf(v2, x2.x, ax); ay = fmaf(v2, x2.y, ay);
            ax = fmaf(v3, x3.x, ax); ay = fmaf(v3, x3.y, ay);
        }
        for (; j < m; j++) {
            int   c = __shfl_sync(0xffffffffu, ed.x, j);
            float v = __int_as_float(__shfl_sync(0xffffffffu, ed.y, j));
            float2 xv = __half22float2(*((const __half2*)(in + (size_t)c * F_OUT) + lane));
            ax = fmaf(v, xv.x, ax); ay = fmaf(v, xv.y, ay);
        }
    }

    *(float2*)(out + (size_t)warp * F_OUT + lane * 2) = make_float2(ax, ay);
}

// ---------------------------------------------------------------------------
// Finalize
// ---------------------------------------------------------------------------
__global__ void finalize(const float* __restrict__ s0, const float* __restrict__ a,
                         float* __restrict__ out_hp, float* __restrict__ out_att)
{
    __shared__ float ch[8][6][64];
    __shared__ float as[768];

    const int tid = threadIdx.x;
    for (int i = tid; i < 768; i += 256) as[i] = a[i];

    const int w    = tid >> 5;
    const int lane = tid & 31;
    const int r    = blockIdx.x * 8 + w;
    __syncthreads();

    #pragma unroll
    for (int c = 0; c < 6; c++) {
        float v0 = g_acc[c][(size_t)r * F_OUT + lane];
        float v1 = g_acc[c][(size_t)r * F_OUT + lane + 32];
        if (c >= 3) { v0 = fabsf(v0); v1 = fabsf(v1); }
        ch[w][c][lane]      = v0;
        ch[w][c][lane + 32] = v1;
    }
    __syncwarp();

    float p[6];
    if (r < N_NODES / 2) {
        size_t b0 = (size_t)(2 * r) * F_OUT;
        size_t b1 = (size_t)(2 * r + 1) * F_OUT;
        float u0 = s0[b0 + lane], u1 = s0[b0 + lane + 32];
        float w0 = s0[b1 + lane], w1 = s0[b1 + lane + 32];
        #pragma unroll
        for (int i = 0; i < 6; i++) {
            const float* ai = as + i * 128;
            p[i] = ai[lane] * u0 + ai[lane + 32] * u1
                 + ai[64 + lane] * w0 + ai[96 + lane] * w1;
        }
    } else {
        int q = 2 * r - N_NODES;
        #pragma unroll
        for (int i = 0; i < 6; i++) {
            float u0 = g_acc[i][(size_t)q * F_OUT + lane];
            float u1 = g_acc[i][(size_t)q * F_OUT + lane + 32];
            float w0 = g_acc[i][(size_t)(q + 1) * F_OUT + lane];
            float w1 = g_acc[i][(size_t)(q + 1) * F_OUT + lane + 32];
            if (i >= 3) { u0 = fabsf(u0); u1 = fabsf(u1); w0 = fabsf(w0); w1 = fabsf(w1); }
            const float* ai = as + i * 128;
            p[i] = ai[lane] * u0 + ai[lane + 32] * u1
                 + ai[64 + lane] * w0 + ai[96 + lane] * w1;
        }
    }

    #pragma unroll
    for (int i = 0; i < 6; i++) {
        #pragma unroll
        for (int off = 16; off; off >>= 1)
            p[i] += __shfl_down_sync(0xffffffffu, p[i], off);
        p[i] = __shfl_sync(0xffffffffu, p[i], 0);
    }

    float m = p[0];
    #pragma unroll
    for (int i = 1; i < 6; i++) m = fmaxf(m, p[i]);
    float att[6], s = 0.f;
    #pragma unroll
    for (int i = 0; i < 6; i++) { att[i] = expf(p[i] - m); s += att[i]; }
    float inv = 1.f / s;
    #pragma unroll
    for (int i = 0; i < 6; i++) att[i] *= inv;

    if (out_att && lane == 0) {
        #pragma unroll
        for (int i = 0; i < 6; i++) out_att[(size_t)r * 6 + i] = att[i];
    }

    #pragma unroll
    for (int kk = 0; kk < 2; kk++) {
        int k = lane + kk * 32;
        float hp = 0.f;
        #pragma unroll
        for (int j = 0; j < 6; j++) {
            int idx = j * 64 + k;
            hp = fmaf(att[j], ch[w][idx % 6][idx / 6], hp);
        }
        out_hp[(size_t)r * F_OUT + k] = hp * (1.0f / 6.0f);
    }
}

// ---------------------------------------------------------------------------
extern "C" void kernel_launch(void* const* d_in, const int* in_sizes, int n_in,
                              void* d_out, int out_size)
{
    const float* x  = (const float*)d_in[0];
    const float* W  = (const float*)d_in[1];
    const float* a  = (const float*)d_in[2];
    const int*   iA  = (const int*)d_in[3];   const float* vA  = (const float*)d_in[4];
    const int*   iP1 = (const int*)d_in[5];   const float* vP1 = (const float*)d_in[6];
    const int*   iP2 = (const int*)d_in[7];   const float* vP2 = (const float*)d_in[8];
    const int*   iP3 = (const int*)d_in[9];   const float* vP3 = (const float*)d_in[10];

    float*  s0;   cudaGetSymbolAddress((void**)&s0,  g_s0);
    __half* s0h;  cudaGetSymbolAddress((void**)&s0h, g_s0h);
    float*  acc;  cudaGetSymbolAddress((void**)&acc, g_acc);
    int*    cnt;  cudaGetSymbolAddress((void**)&cnt, g_cnt);
    int*    rp;   cudaGetSymbolAddress((void**)&rp,  g_rowptr);
    int*    rk;   cudaGetSymbolAddress((void**)&rk,  g_rank);
    int2*   eg;   cudaGetSymbolAddress((void**)&eg,  g_edges);
    int*    bs;   cudaGetSymbolAddress((void**)&bs,  g_bsum);
    int*    bsx;  cudaGetSymbolAddress((void**)&bsx, g_bsumx);

    gemm64<<<(N_NODES + 63) / 64, 128>>>(x, W, s0, s0h);

    cudaMemsetAsync(cnt, 0, sizeof(int) * 4 * N_NODES, 0);
    const dim3 EG((N_EDGES + 255) / 256, 4);
    hist_rank<<<EG, 256>>>(iA, iP1, iP2, iP3, cnt, rk);
    scan_blocks<<<dim3(NB_SCAN, 4), 256>>>(cnt, rp, bs);
    scan_bsums<<<1, 128>>>(bs, bsx);
    scan_addback<<<dim3((N_NODES + 256) / 256, 4), 256>>>(bsx, rp);
    scatter_edges<<<EG, 256>>>(iA, iP1, iP2, iP3, vA, vP1, vP2, vP3, rp, rk, eg);

    const int SG = (N_NODES * 32 + 255) / 256;
    // A chain (fp32 gather)
    spmm_csr<<<SG, 256>>>(rp, eg, s0, acc + 0 * (size_t)NF);
    spmm_csr<<<SG, 256>>>(rp, eg, acc + 0 * (size_t)NF, acc + 1 * (size_t)NF);
    spmm_csr<<<SG, 256>>>(rp, eg, acc + 1 * (size_t)NF, acc + 2 * (size_t)NF);
    // P1..P3 fused (fp16 gather, fp32 accumulate)
    spmm_csr_h3<<<dim3(SG, 3), 256>>>(rp, eg, s0h, acc);

    float* out = (float*)d_out;
    float* att = (out_size >= N_NODES * F_OUT + N_NODES * 6)
                     ? out + (size_t)N_NODES * F_OUT : nullptr;
    finalize<<<N_NODES / 8, 256>>>(s0, a, out, att);
}

// round 5
// speedup vs baseline: 1.3560x; 1.0813x over previous
#include <cuda_runtime.h>
#include <cuda_fp16.h>
#include <cstddef>

#define N_NODES 100000
#define N_EDGES 3200000
#define F_IN    256
#define F_OUT   64
#define NF      (N_NODES * F_OUT)
#define SCAN_BLK 1024
#define NB_SCAN  ((N_NODES + SCAN_BLK - 1) / SCAN_BLK)   // 98

// Scratch (device globals; allocation-free).
__device__ float  g_s0[NF];
__device__ __half g_s0h[NF];             // fp16 s0 (gather source, hop 1 + P ops)
__device__ __half g_h1h[NF];             // fp16 h_A  (gather source, hop 2)
__device__ __half g_h2h[NF];             // fp16 h_A2 (gather source, hop 3)
__device__ float  g_acc[6][NF];          // hA, hA2, hA3, hs1, hs2, hs3
__device__ int    g_cnt[4][N_NODES];
__device__ int    g_rowptr[4][N_NODES + 1];
__device__ int    g_rank[4][N_EDGES];
__device__ int2   g_edges[4][N_EDGES];
__device__ int    g_bsum[4][NB_SCAN + 1];
__device__ int    g_bsumx[4][NB_SCAN + 1];

// ---------------------------------------------------------------------------
// GEMM: s0[N,64] = x[N,256] @ W[256,64], fp32; also emits fp16 copy.
// ---------------------------------------------------------------------------
__global__ void gemm64(const float* __restrict__ x, const float* __restrict__ W,
                       float* __restrict__ out, __half* __restrict__ outh)
{
    __shared__ float xs[32][64];
    __shared__ float ws[32][64];

    const int tid = threadIdx.x;       // 0..127
    const int tx  = tid & 7;
    const int ty  = tid >> 3;
    const int r0  = blockIdx.x * 64;

    float4 acc0[4] = {};
    float4 acc1[4] = {};

    for (int k0 = 0; k0 < F_IN; k0 += 32) {
        #pragma unroll
        for (int it = 0; it < 4; it++) {
            int li  = it * 128 + tid;
            int row = li >> 3;
            int kq  = li & 7;
            float4 v = make_float4(0.f, 0.f, 0.f, 0.f);
            int gr = r0 + row;
            if (gr < N_NODES)
                v = *(const float4*)(x + (size_t)gr * F_IN + k0 + kq * 4);
            xs[kq * 4 + 0][row] = v.x;
            xs[kq * 4 + 1][row] = v.y;
            xs[kq * 4 + 2][row] = v.z;
            xs[kq * 4 + 3][row] = v.w;
        }
        #pragma unroll
        for (int it = 0; it < 4; it++) {
            int li = it * 128 + tid;
            int kk = li >> 4;
            int cq = li & 15;
            *(float4*)&ws[kk][cq * 4] =
                *(const float4*)(W + (size_t)(k0 + kk) * F_OUT + cq * 4);
        }
        __syncthreads();

        #pragma unroll
        for (int kk = 0; kk < 32; kk++) {
            float4 av = *(const float4*)&xs[kk][ty * 4];
            float4 b0 = *(const float4*)&ws[kk][tx * 4];
            float4 b1 = *(const float4*)&ws[kk][tx * 4 + 32];
            float a4[4] = {av.x, av.y, av.z, av.w};
            #pragma unroll
            for (int j = 0; j < 4; j++) {
                acc0[j].x = fmaf(a4[j], b0.x, acc0[j].x);
                acc0[j].y = fmaf(a4[j], b0.y, acc0[j].y);
                acc0[j].z = fmaf(a4[j], b0.z, acc0[j].z);
                acc0[j].w = fmaf(a4[j], b0.w, acc0[j].w);
                acc1[j].x = fmaf(a4[j], b1.x, acc1[j].x);
                acc1[j].y = fmaf(a4[j], b1.y, acc1[j].y);
                acc1[j].z = fmaf(a4[j], b1.z, acc1[j].z);
                acc1[j].w = fmaf(a4[j], b1.w, acc1[j].w);
            }
        }
        __syncthreads();
    }

    #pragma unroll
    for (int j = 0; j < 4; j++) {
        int gr = r0 + ty * 4 + j;
        if (gr < N_NODES) {
            *(float4*)(out + (size_t)gr * F_OUT + tx * 4)      = acc0[j];
            *(float4*)(out + (size_t)gr * F_OUT + tx * 4 + 32) = acc1[j];
            __half2* hp = (__half2*)(outh + (size_t)gr * F_OUT);
            hp[tx * 2]      = __floats2half2_rn(acc0[j].x, acc0[j].y);
            hp[tx * 2 + 1]  = __floats2half2_rn(acc0[j].z, acc0[j].w);
            hp[tx * 2 + 16] = __floats2half2_rn(acc1[j].x, acc1[j].y);
            hp[tx * 2 + 17] = __floats2half2_rn(acc1[j].z, acc1[j].w);
        }
    }
}

// ---------------------------------------------------------------------------
// CSR build (fused across 4 operators via blockIdx.y)
// ---------------------------------------------------------------------------
__global__ void hist_rank(const int* __restrict__ i0, const int* __restrict__ i1,
                          const int* __restrict__ i2, const int* __restrict__ i3,
                          int* __restrict__ cnt, int* __restrict__ rank)
{
    const int op = blockIdx.y;
    const int* idx = (op == 0) ? i0 : (op == 1) ? i1 : (op == 2) ? i2 : i3;
    int e = blockIdx.x * blockDim.x + threadIdx.x;
    if (e < N_EDGES) {
        int r = idx[e];
        rank[(size_t)op * N_EDGES + e] = atomicAdd(&cnt[op * N_NODES + r], 1);
    }
}

__global__ void scan_blocks(const int* __restrict__ cnt, int* __restrict__ excl,
                            int* __restrict__ bsum)
{
    __shared__ int sh[256];
    const int op = blockIdx.y;
    const int t = threadIdx.x;
    const int base = blockIdx.x * SCAN_BLK + t * 4;
    const int* c = cnt + op * N_NODES;
    int* ex = excl + op * (N_NODES + 1);

    int v[4];
    #pragma unroll
    for (int i = 0; i < 4; i++)
        v[i] = (base + i < N_NODES) ? c[base + i] : 0;
    int s = v[0] + v[1] + v[2] + v[3];
    sh[t] = s;
    __syncthreads();
    #pragma unroll
    for (int off = 1; off < 256; off <<= 1) {
        int x = (t >= off) ? sh[t - off] : 0;
        __syncthreads();
        sh[t] += x;
        __syncthreads();
    }
    int run = sh[t] - s;
    #pragma unroll
    for (int i = 0; i < 4; i++) {
        if (base + i < N_NODES) ex[base + i] = run;
        run += v[i];
    }
    if (t == 255) bsum[op * (NB_SCAN + 1) + blockIdx.x] = sh[255];
}

__global__ void scan_bsums(const int* __restrict__ bsum, int* __restrict__ bsumx)
{
    const int op   = threadIdx.x >> 5;
    const int lane = threadIdx.x & 31;
    const int* b = bsum  + op * (NB_SCAN + 1);
    int*      bx = bsumx + op * (NB_SCAN + 1);
    int carry = 0;
    #pragma unroll
    for (int c = 0; c < (NB_SCAN + 31) / 32; c++) {
        int i = c * 32 + lane;
        int v = (i < NB_SCAN) ? b[i] : 0;
        int s = v;
        #pragma unroll
        for (int off = 1; off < 32; off <<= 1) {
            int t = __shfl_up_sync(0xffffffffu, s, off);
            if (lane >= off) s += t;
        }
        if (i < NB_SCAN) bx[i] = carry + s - v;
        carry += __shfl_sync(0xffffffffu, s, 31);
    }
}

__global__ void scan_addback(const int* __restrict__ bsumx, int* __restrict__ rowptr)
{
    const int op = blockIdx.y;
    int i = blockIdx.x * blockDim.x + threadIdx.x;
    int* rp = rowptr + op * (N_NODES + 1);
    if (i < N_NODES)
        rp[i] += bsumx[op * (NB_SCAN + 1) + (i >> 10)];
    if (i == N_NODES) rp[N_NODES] = N_EDGES;
}

__global__ void scatter_edges(const int* __restrict__ i0, const int* __restrict__ i1,
                              const int* __restrict__ i2, const int* __restrict__ i3,
                              const float* __restrict__ v0, const float* __restrict__ v1,
                              const float* __restrict__ v2, const float* __restrict__ v3,
                              const int* __restrict__ rowptr, const int* __restrict__ rank,
                              int2* __restrict__ out)
{
    const int op = blockIdx.y;
    const int*   idx = (op == 0) ? i0 : (op == 1) ? i1 : (op == 2) ? i2 : i3;
    const float* val = (op == 0) ? v0 : (op == 1) ? v1 : (op == 2) ? v2 : v3;
    int e = blockIdx.x * blockDim.x + threadIdx.x;
    if (e < N_EDGES) {
        int   r = idx[e];
        int   c = idx[N_EDGES + e];
        float v = val[e];
        int pos = rowptr[op * (N_NODES + 1) + r] + rank[(size_t)op * N_EDGES + e];
        out[(size_t)op * N_EDGES + pos] = make_int2(c, __float_as_int(v));
    }
}

// ---------------------------------------------------------------------------
// CSR SPMM core: fp16 gather, fp32 accumulate; optional fp16 output copy.
// ---------------------------------------------------------------------------
__device__ __forceinline__ void spmm_row_h(const int* rowptr, const int2* eg,
                                           const __half* in, float* out,
                                           __half* outh, int warp, int lane)
{
    const int s = rowptr[warp];
    const int e = rowptr[warp + 1];
    float ax = 0.f, ay = 0.f;

    for (int b = s; b < e; b += 32) {
        const int m = min(32, e - b);
        int2 ed = make_int2(0, 0);
        if (lane < m) ed = eg[b + lane];

        int j = 0;
        for (; j + 4 <= m; j += 4) {
            int   c0 = __shfl_sync(0xffffffffu, ed.x, j);
            int   c1 = __shfl_sync(0xffffffffu, ed.x, j + 1);
            int   c2 = __shfl_sync(0xffffffffu, ed.x, j + 2);
            int   c3 = __shfl_sync(0xffffffffu, ed.x, j + 3);
            float v0 = __int_as_float(__shfl_sync(0xffffffffu, ed.y, j));
            float v1 = __int_as_float(__shfl_sync(0xffffffffu, ed.y, j + 1));
            float v2 = __int_as_float(__shfl_sync(0xffffffffu, ed.y, j + 2));
            float v3 = __int_as_float(__shfl_sync(0xffffffffu, ed.y, j + 3));
            float2 x0 = __half22float2(*((const __half2*)(in + (size_t)c0 * F_OUT) + lane));
            float2 x1 = __half22float2(*((const __half2*)(in + (size_t)c1 * F_OUT) + lane));
            float2 x2 = __half22float2(*((const __half2*)(in + (size_t)c2 * F_OUT) + lane));
            float2 x3 = __half22float2(*((const __half2*)(in + (size_t)c3 * F_OUT) + lane));
            ax = fmaf(v0, x0.x, ax); ay = fmaf(v0, x0.y, ay);
            ax = fmaf(v1, x1.x, ax); ay = fmaf(v1, x1.y, ay);
            ax = fmaf(v2, x2.x, ax); ay = fmaf(v2, x2.y, ay);
            ax = fmaf(v3, x3.x, ax); ay = fmaf(v3, x3.y, ay);
        }
        for (; j < m; j++) {
            int   c = __shfl_sync(0xffffffffu, ed.x, j);
            float v = __int_as_float(__shfl_sync(0xffffffffu, ed.y, j));
            float2 xv = __half22float2(*((const __half2*)(in + (size_t)c * F_OUT) + lane));
            ax = fmaf(v, xv.x, ax); ay = fmaf(v, xv.y, ay);
        }
    }

    *(float2*)(out + (size_t)warp * F_OUT + lane * 2) = make_float2(ax, ay);
    if (outh)
        *((__half2*)(outh + (size_t)warp * F_OUT) + lane) = __floats2half2_rn(ax, ay);
}

// Fused launch: y=0 -> A·s0 (writes acc0 + h1h), y=1..3 -> P1..P3 (acc3..5).
__global__ void spmm_fused4(const int* __restrict__ rowptr_all,
                            const int2* __restrict__ eg_all,
                            const __half* __restrict__ s0h,
                            float* __restrict__ acc_all,
                            __half* __restrict__ h1h)
{
    const int op = blockIdx.y;                       // 0..3
    const int warp = (blockIdx.x * blockDim.x + threadIdx.x) >> 5;
    const int lane = threadIdx.x & 31;
    if (warp >= N_NODES) return;

    const int*  rowptr = rowptr_all + op * (N_NODES + 1);
    const int2* eg     = eg_all + (size_t)op * N_EDGES;
    float* out  = (op == 0) ? acc_all : acc_all + (size_t)(op + 2) * NF;
    __half* oh  = (op == 0) ? h1h : nullptr;
    spmm_row_h(rowptr, eg, s0h, out, oh, warp, lane);
}

// Single chain hop: A gather from fp16 'in', write fp32 + optional fp16.
__global__ void spmm_hop(const int* __restrict__ rowptr, const int2* __restrict__ eg,
                         const __half* __restrict__ in, float* __restrict__ out,
                         __half* __restrict__ outh)
{
    const int warp = (blockIdx.x * blockDim.x + threadIdx.x) >> 5;
    const int lane = threadIdx.x & 31;
    if (warp >= N_NODES) return;
    spmm_row_h(rowptr, eg, in, out, outh, warp, lane);
}

// ---------------------------------------------------------------------------
// Finalize
// ---------------------------------------------------------------------------
__global__ void finalize(const float* __restrict__ s0, const float* __restrict__ a,
                         float* __restrict__ out_hp, float* __restrict__ out_att)
{
    __shared__ float ch[8][6][64];
    __shared__ float as[768];

    const int tid = threadIdx.x;
    for (int i = tid; i < 768; i += 256) as[i] = a[i];

    const int w    = tid >> 5;
    const int lane = tid & 31;
    const int r    = blockIdx.x * 8 + w;
    __syncthreads();

    #pragma unroll
    for (int c = 0; c < 6; c++) {
        float v0 = g_acc[c][(size_t)r * F_OUT + lane];
        float v1 = g_acc[c][(size_t)r * F_OUT + lane + 32];
        if (c >= 3) { v0 = fabsf(v0); v1 = fabsf(v1); }
        ch[w][c][lane]      = v0;
        ch[w][c][lane + 32] = v1;
    }
    __syncwarp();

    float p[6];
    if (r < N_NODES / 2) {
        size_t b0 = (size_t)(2 * r) * F_OUT;
        size_t b1 = (size_t)(2 * r + 1) * F_OUT;
        float u0 = s0[b0 + lane], u1 = s0[b0 + lane + 32];
        float w0 = s0[b1 + lane], w1 = s0[b1 + lane + 32];
        #pragma unroll
        for (int i = 0; i < 6; i++) {
            const float* ai = as + i * 128;
            p[i] = ai[lane] * u0 + ai[lane + 32] * u1
                 + ai[64 + lane] * w0 + ai[96 + lane] * w1;
        }
    } else {
        int q = 2 * r - N_NODES;
        #pragma unroll
        for (int i = 0; i < 6; i++) {
            float u0 = g_acc[i][(size_t)q * F_OUT + lane];
            float u1 = g_acc[i][(size_t)q * F_OUT + lane + 32];
            float w0 = g_acc[i][(size_t)(q + 1) * F_OUT + lane];
            float w1 = g_acc[i][(size_t)(q + 1) * F_OUT + lane + 32];
            if (i >= 3) { u0 = fabsf(u0); u1 = fabsf(u1); w0 = fabsf(w0); w1 = fabsf(w1); }
            const float* ai = as + i * 128;
            p[i] = ai[lane] * u0 + ai[lane + 32] * u1
                 + ai[64 + lane] * w0 + ai[96 + lane] * w1;
        }
    }

    #pragma unroll
    for (int i = 0; i < 6; i++) {
        #pragma unroll
        for (int off = 16; off; off >>= 1)
            p[i] += __shfl_down_sync(0xffffffffu, p[i], off);
        p[i] = __shfl_sync(0xffffffffu, p[i], 0);
    }

    float m = p[0];
    #pragma unroll
    for (int i = 1; i < 6; i++) m = fmaxf(m, p[i]);
    float att[6], s = 0.f;
    #pragma unroll
    for (int i = 0; i < 6; i++) { att[i] = expf(p[i] - m); s += att[i]; }
    float inv = 1.f / s;
    #pragma unroll
    for (int i = 0; i < 6; i++) att[i] *= inv;

    if (out_att && lane == 0) {
        #pragma unroll
        for (int i = 0; i < 6; i++) out_att[(size_t)r * 6 + i] = att[i];
    }

    #pragma unroll
    for (int kk = 0; kk < 2; kk++) {
        int k = lane + kk * 32;
        float hp = 0.f;
        #pragma unroll
        for (int j = 0; j < 6; j++) {
            int idx = j * 64 + k;
            hp = fmaf(att[j], ch[w][idx % 6][idx / 6], hp);
        }
        out_hp[(size_t)r * F_OUT + k] = hp * (1.0f / 6.0f);
    }
}

// ---------------------------------------------------------------------------
extern "C" void kernel_launch(void* const* d_in, const int* in_sizes, int n_in,
                              void* d_out, int out_size)
{
    const float* x  = (const float*)d_in[0];
    const float* W  = (const float*)d_in[1];
    const float* a  = (const float*)d_in[2];
    const int*   iA  = (const int*)d_in[3];   const float* vA  = (const float*)d_in[4];
    const int*   iP1 = (const int*)d_in[5];   const float* vP1 = (const float*)d_in[6];
    const int*   iP2 = (const int*)d_in[7];   const float* vP2 = (const float*)d_in[8];
    const int*   iP3 = (const int*)d_in[9];   const float* vP3 = (const float*)d_in[10];

    float*  s0;   cudaGetSymbolAddress((void**)&s0,  g_s0);
    __half* s0h;  cudaGetSymbolAddress((void**)&s0h, g_s0h);
    __half* h1h;  cudaGetSymbolAddress((void**)&h1h, g_h1h);
    __half* h2h;  cudaGetSymbolAddress((void**)&h2h, g_h2h);
    float*  acc;  cudaGetSymbolAddress((void**)&acc, g_acc);
    int*    cnt;  cudaGetSymbolAddress((void**)&cnt, g_cnt);
    int*    rp;   cudaGetSymbolAddress((void**)&rp,  g_rowptr);
    int*    rk;   cudaGetSymbolAddress((void**)&rk,  g_rank);
    int2*   eg;   cudaGetSymbolAddress((void**)&eg,  g_edges);
    int*    bs;   cudaGetSymbolAddress((void**)&bs,  g_bsum);
    int*    bsx;  cudaGetSymbolAddress((void**)&bsx, g_bsumx);

    gemm64<<<(N_NODES + 63) / 64, 128>>>(x, W, s0, s0h);

    cudaMemsetAsync(cnt, 0, sizeof(int) * 4 * N_NODES, 0);
    const dim3 EG((N_EDGES + 255) / 256, 4);
    hist_rank<<<EG, 256>>>(iA, iP1, iP2, iP3, cnt, rk);
    scan_blocks<<<dim3(NB_SCAN, 4), 256>>>(cnt, rp, bs);
    scan_bsums<<<1, 128>>>(bs, bsx);
    scan_addback<<<dim3((N_NODES + 256) / 256, 4), 256>>>(bsx, rp);
    scatter_edges<<<EG, 256>>>(iA, iP1, iP2, iP3, vA, vP1, vP2, vP3, rp, rk, eg);

    const int SG = (N_NODES * 32 + 255) / 256;
    // Fused: A·s0 -> acc0+h1h, P1..P3 -> acc3..5 (all fp16 gather from s0h)
    spmm_fused4<<<dim3(SG, 4), 256>>>(rp, eg, s0h, acc, h1h);
    // Chain hops 2,3
    spmm_hop<<<SG, 256>>>(rp, eg, h1h, acc + 1 * (size_t)NF, h2h);
    spmm_hop<<<SG, 256>>>(rp, eg, h2h, acc + 2 * (size_t)NF, nullptr);

    float* out = (float*)d_out;
    float* att = (out_size >= N_NODES * F_OUT + N_NODES * 6)
                     ? out + (size_t)N_NODES * F_OUT : nullptr;
    finalize<<<N_NODES / 8, 256>>>(s0, a, out, att);
}

// round 6
// speedup vs baseline: 1.4059x; 1.0368x over previous
#include <cuda_runtime.h>
#include <cuda_fp16.h>
#include <cstddef>

#define N_NODES 100000
#define N_EDGES 3200000
#define F_IN    256
#define F_OUT   64
#define NF      (N_NODES * F_OUT)
#define SCAN_BLK 1024
#define NB_SCAN  ((N_NODES + SCAN_BLK - 1) / SCAN_BLK)   // 98

// Scratch (device globals; allocation-free).
__device__ float  g_s0[NF];
__device__ __half g_s0h[NF];             // fp16 s0 (gather source, hop 1 + P ops)
__device__ __half g_h1h[NF];             // fp16 h_A  (gather source, hop 2)
__device__ __half g_h2h[NF];             // fp16 h_A2 (gather source, hop 3)
__device__ float  g_acc[6][NF];          // hA, hA2, hA3, hs1, hs2, hs3
__device__ int    g_cnt[4][N_NODES];
__device__ int    g_rowptr[4][N_NODES + 1];
__device__ int    g_rank[4][N_EDGES];
__device__ int2   g_edges[4][N_EDGES];
__device__ int    g_bsum[4][NB_SCAN + 1];
__device__ int    g_bsumx[4][NB_SCAN + 1];

// ---------------------------------------------------------------------------
// GEMM: s0[N,64] = x[N,256] @ W[256,64], fp32; also emits fp16 copy.
// ---------------------------------------------------------------------------
__global__ void gemm64(const float* __restrict__ x, const float* __restrict__ W,
                       float* __restrict__ out, __half* __restrict__ outh)
{
    __shared__ float xs[32][64];
    __shared__ float ws[32][64];

    const int tid = threadIdx.x;       // 0..127
    const int tx  = tid & 7;
    const int ty  = tid >> 3;
    const int r0  = blockIdx.x * 64;

    float4 acc0[4] = {};
    float4 acc1[4] = {};

    for (int k0 = 0; k0 < F_IN; k0 += 32) {
        #pragma unroll
        for (int it = 0; it < 4; it++) {
            int li  = it * 128 + tid;
            int row = li >> 3;
            int kq  = li & 7;
            float4 v = make_float4(0.f, 0.f, 0.f, 0.f);
            int gr = r0 + row;
            if (gr < N_NODES)
                v = *(const float4*)(x + (size_t)gr * F_IN + k0 + kq * 4);
            xs[kq * 4 + 0][row] = v.x;
            xs[kq * 4 + 1][row] = v.y;
            xs[kq * 4 + 2][row] = v.z;
            xs[kq * 4 + 3][row] = v.w;
        }
        #pragma unroll
        for (int it = 0; it < 4; it++) {
            int li = it * 128 + tid;
            int kk = li >> 4;
            int cq = li & 15;
            *(float4*)&ws[kk][cq * 4] =
                *(const float4*)(W + (size_t)(k0 + kk) * F_OUT + cq * 4);
        }
        __syncthreads();

        #pragma unroll
        for (int kk = 0; kk < 32; kk++) {
            float4 av = *(const float4*)&xs[kk][ty * 4];
            float4 b0 = *(const float4*)&ws[kk][tx * 4];
            float4 b1 = *(const float4*)&ws[kk][tx * 4 + 32];
            float a4[4] = {av.x, av.y, av.z, av.w};
            #pragma unroll
            for (int j = 0; j < 4; j++) {
                acc0[j].x = fmaf(a4[j], b0.x, acc0[j].x);
                acc0[j].y = fmaf(a4[j], b0.y, acc0[j].y);
                acc0[j].z = fmaf(a4[j], b0.z, acc0[j].z);
                acc0[j].w = fmaf(a4[j], b0.w, acc0[j].w);
                acc1[j].x = fmaf(a4[j], b1.x, acc1[j].x);
                acc1[j].y = fmaf(a4[j], b1.y, acc1[j].y);
                acc1[j].z = fmaf(a4[j], b1.z, acc1[j].z);
                acc1[j].w = fmaf(a4[j], b1.w, acc1[j].w);
            }
        }
        __syncthreads();
    }

    #pragma unroll
    for (int j = 0; j < 4; j++) {
        int gr = r0 + ty * 4 + j;
        if (gr < N_NODES) {
            *(float4*)(out + (size_t)gr * F_OUT + tx * 4)      = acc0[j];
            *(float4*)(out + (size_t)gr * F_OUT + tx * 4 + 32) = acc1[j];
            __half2* hp = (__half2*)(outh + (size_t)gr * F_OUT);
            hp[tx * 2]      = __floats2half2_rn(acc0[j].x, acc0[j].y);
            hp[tx * 2 + 1]  = __floats2half2_rn(acc0[j].z, acc0[j].w);
            hp[tx * 2 + 16] = __floats2half2_rn(acc1[j].x, acc1[j].y);
            hp[tx * 2 + 17] = __floats2half2_rn(acc1[j].z, acc1[j].w);
        }
    }
}

// ---------------------------------------------------------------------------
// CSR build (fused across 4 operators via blockIdx.y)
// ---------------------------------------------------------------------------
__global__ void hist_rank(const int* __restrict__ i0, const int* __restrict__ i1,
                          const int* __restrict__ i2, const int* __restrict__ i3,
                          int* __restrict__ cnt, int* __restrict__ rank)
{
    const int op = blockIdx.y;
    const int* idx = (op == 0) ? i0 : (op == 1) ? i1 : (op == 2) ? i2 : i3;
    int e = blockIdx.x * blockDim.x + threadIdx.x;
    if (e < N_EDGES) {
        int r = idx[e];
        rank[(size_t)op * N_EDGES + e] = atomicAdd(&cnt[op * N_NODES + r], 1);
    }
}

__global__ void scan_blocks(const int* __restrict__ cnt, int* __restrict__ excl,
                            int* __restrict__ bsum)
{
    __shared__ int sh[256];
    const int op = blockIdx.y;
    const int t = threadIdx.x;
    const int base = blockIdx.x * SCAN_BLK + t * 4;
    const int* c = cnt + op * N_NODES;
    int* ex = excl + op * (N_NODES + 1);

    int v[4];
    #pragma unroll
    for (int i = 0; i < 4; i++)
        v[i] = (base + i < N_NODES) ? c[base + i] : 0;
    int s = v[0] + v[1] + v[2] + v[3];
    sh[t] = s;
    __syncthreads();
    #pragma unroll
    for (int off = 1; off < 256; off <<= 1) {
        int x = (t >= off) ? sh[t - off] : 0;
        __syncthreads();
        sh[t] += x;
        __syncthreads();
    }
    int run = sh[t] - s;
    #pragma unroll
    for (int i = 0; i < 4; i++) {
        if (base + i < N_NODES) ex[base + i] = run;
        run += v[i];
    }
    if (t == 255) bsum[op * (NB_SCAN + 1) + blockIdx.x] = sh[255];
}

__global__ void scan_bsums(const int* __restrict__ bsum, int* __restrict__ bsumx)
{
    const int op   = threadIdx.x >> 5;
    const int lane = threadIdx.x & 31;
    const int* b = bsum  + op * (NB_SCAN + 1);
    int*      bx = bsumx + op * (NB_SCAN + 1);
    int carry = 0;
    #pragma unroll
    for (int c = 0; c < (NB_SCAN + 31) / 32; c++) {
        int i = c * 32 + lane;
        int v = (i < NB_SCAN) ? b[i] : 0;
        int s = v;
        #pragma unroll
        for (int off = 1; off < 32; off <<= 1) {
            int t = __shfl_up_sync(0xffffffffu, s, off);
            if (lane >= off) s += t;
        }
        if (i < NB_SCAN) bx[i] = carry + s - v;
        carry += __shfl_sync(0xffffffffu, s, 31);
    }
}

__global__ void scan_addback(const int* __restrict__ bsumx, int* __restrict__ rowptr)
{
    const int op = blockIdx.y;
    int i = blockIdx.x * blockDim.x + threadIdx.x;
    int* rp = rowptr + op * (N_NODES + 1);
    if (i < N_NODES)
        rp[i] += bsumx[op * (NB_SCAN + 1) + (i >> 10)];
    if (i == N_NODES) rp[N_NODES] = N_EDGES;
}

__global__ void scatter_edges(const int* __restrict__ i0, const int* __restrict__ i1,
                              const int* __restrict__ i2, const int* __restrict__ i3,
                              const float* __restrict__ v0, const float* __restrict__ v1,
                              const float* __restrict__ v2, const float* __restrict__ v3,
                              const int* __restrict__ rowptr, const int* __restrict__ rank,
                              int2* __restrict__ out)
{
    const int op = blockIdx.y;
    const int*   idx = (op == 0) ? i0 : (op == 1) ? i1 : (op == 2) ? i2 : i3;
    const float* val = (op == 0) ? v0 : (op == 1) ? v1 : (op == 2) ? v2 : v3;
    int e = blockIdx.x * blockDim.x + threadIdx.x;
    if (e < N_EDGES) {
        int   r = idx[e];
        int   c = idx[N_EDGES + e];
        float v = val[e];
        int pos = rowptr[op * (N_NODES + 1) + r] + rank[(size_t)op * N_EDGES + e];
        out[(size_t)op * N_EDGES + pos] = make_int2(c, __float_as_int(v));
    }
}

// ---------------------------------------------------------------------------
// CSR SPMM core: fp16 gather, fp32 accumulate; optional fp16 output copy.
// ---------------------------------------------------------------------------
__device__ __forceinline__ void spmm_row_h(const int* rowptr, const int2* eg,
                                           const __half* in, float* out,
                                           __half* outh, int warp, int lane)
{
    const int s = rowptr[warp];
    const int e = rowptr[warp + 1];
    float ax = 0.f, ay = 0.f;

    for (int b = s; b < e; b += 32) {
        const int m = min(32, e - b);
        int2 ed = make_int2(0, 0);
        if (lane < m) ed = eg[b + lane];

        int j = 0;
        for (; j + 4 <= m; j += 4) {
            int   c0 = __shfl_sync(0xffffffffu, ed.x, j);
            int   c1 = __shfl_sync(0xffffffffu, ed.x, j + 1);
            int   c2 = __shfl_sync(0xffffffffu, ed.x, j + 2);
            int   c3 = __shfl_sync(0xffffffffu, ed.x, j + 3);
            float v0 = __int_as_float(__shfl_sync(0xffffffffu, ed.y, j));
            float v1 = __int_as_float(__shfl_sync(0xffffffffu, ed.y, j + 1));
            float v2 = __int_as_float(__shfl_sync(0xffffffffu, ed.y, j + 2));
            float v3 = __int_as_float(__shfl_sync(0xffffffffu, ed.y, j + 3));
            float2 x0 = __half22float2(*((const __half2*)(in + (size_t)c0 * F_OUT) + lane));
            float2 x1 = __half22float2(*((const __half2*)(in + (size_t)c1 * F_OUT) + lane));
            float2 x2 = __half22float2(*((const __half2*)(in + (size_t)c2 * F_OUT) + lane));
            float2 x3 = __half22float2(*((const __half2*)(in + (size_t)c3 * F_OUT) + lane));
            ax = fmaf(v0, x0.x, ax); ay = fmaf(v0, x0.y, ay);
            ax = fmaf(v1, x1.x, ax); ay = fmaf(v1, x1.y, ay);
            ax = fmaf(v2, x2.x, ax); ay = fmaf(v2, x2.y, ay);
            ax = fmaf(v3, x3.x, ax); ay = fmaf(v3, x3.y, ay);
        }
        for (; j < m; j++) {
            int   c = __shfl_sync(0xffffffffu, ed.x, j);
            float v = __int_as_float(__shfl_sync(0xffffffffu, ed.y, j));
            float2 xv = __half22float2(*((const __half2*)(in + (size_t)c * F_OUT) + lane));
            ax = fmaf(v, xv.x, ax); ay = fmaf(v, xv.y, ay);
        }
    }

    *(float2*)(out + (size_t)warp * F_OUT + lane * 2) = make_float2(ax, ay);
    if (outh)
        *((__half2*)(outh + (size_t)warp * F_OUT) + lane) = __floats2half2_rn(ax, ay);
}

// Fused launch: y=0 -> A·s0 (writes acc0 + h1h), y=1..3 -> P1..P3 (acc3..5).
__global__ void spmm_fused4(const int* __restrict__ rowptr_all,
                            const int2* __restrict__ eg_all,
                            const __half* __restrict__ s0h,
                            float* __restrict__ acc_all,
                            __half* __restrict__ h1h)
{
    const int op = blockIdx.y;                       // 0..3
    const int warp = (blockIdx.x * blockDim.x + threadIdx.x) >> 5;
    const int lane = threadIdx.x & 31;
    if (warp >= N_NODES) return;

    const int*  rowptr = rowptr_all + op * (N_NODES + 1);
    const int2* eg     = eg_all + (size_t)op * N_EDGES;
    float* out  = (op == 0) ? acc_all : acc_all + (size_t)(op + 2) * NF;
    __half* oh  = (op == 0) ? h1h : nullptr;
    spmm_row_h(rowptr, eg, s0h, out, oh, warp, lane);
}

// Single chain hop: A gather from fp16 'in', write fp32 + optional fp16.
__global__ void spmm_hop(const int* __restrict__ rowptr, const int2* __restrict__ eg,
                         const __half* __restrict__ in, float* __restrict__ out,
                         __half* __restrict__ outh)
{
    const int warp = (blockIdx.x * blockDim.x + threadIdx.x) >> 5;
    const int lane = threadIdx.x & 31;
    if (warp >= N_NODES) return;
    spmm_row_h(rowptr, eg, in, out, outh, warp, lane);
}

// ---------------------------------------------------------------------------
// Finalize
// ---------------------------------------------------------------------------
__global__ void finalize(const float* __restrict__ s0, const float* __restrict__ a,
                         float* __restrict__ out_hp, float* __restrict__ out_att)
{
    __shared__ float ch[8][6][64];
    __shared__ float as[768];

    const int tid = threadIdx.x;
    for (int i = tid; i < 768; i += 256) as[i] = a[i];

    const int w    = tid >> 5;
    const int lane = tid & 31;
    const int r    = blockIdx.x * 8 + w;
    __syncthreads();

    #pragma unroll
    for (int c = 0; c < 6; c++) {
        float v0 = g_acc[c][(size_t)r * F_OUT + lane];
        float v1 = g_acc[c][(size_t)r * F_OUT + lane + 32];
        if (c >= 3) { v0 = fabsf(v0); v1 = fabsf(v1); }
        ch[w][c][lane]      = v0;
        ch[w][c][lane + 32] = v1;
    }
    __syncwarp();

    float p[6];
    if (r < N_NODES / 2) {
        size_t b0 = (size_t)(2 * r) * F_OUT;
        size_t b1 = (size_t)(2 * r + 1) * F_OUT;
        float u0 = s0[b0 + lane], u1 = s0[b0 + lane + 32];
        float w0 = s0[b1 + lane], w1 = s0[b1 + lane + 32];
        #pragma unroll
        for (int i = 0; i < 6; i++) {
            const float* ai = as + i * 128;
            p[i] = ai[lane] * u0 + ai[lane + 32] * u1
                 + ai[64 + lane] * w0 + ai[96 + lane] * w1;
        }
    } else {
        int q = 2 * r - N_NODES;
        #pragma unroll
        for (int i = 0; i < 6; i++) {
            float u0 = g_acc[i][(size_t)q * F_OUT + lane];
            float u1 = g_acc[i][(size_t)q * F_OUT + lane + 32];
            float w0 = g_acc[i][(size_t)(q + 1) * F_OUT + lane];
            float w1 = g_acc[i][(size_t)(q + 1) * F_OUT + lane + 32];
            if (i >= 3) { u0 = fabsf(u0); u1 = fabsf(u1); w0 = fabsf(w0); w1 = fabsf(w1); }
            const float* ai = as + i * 128;
            p[i] = ai[lane] * u0 + ai[lane + 32] * u1
                 + ai[64 + lane] * w0 + ai[96 + lane] * w1;
        }
    }

    #pragma unroll
    for (int i = 0; i < 6; i++) {
        #pragma unroll
        for (int off = 16; off; off >>= 1)
            p[i] += __shfl_down_sync(0xffffffffu, p[i], off);
        p[i] = __shfl_sync(0xffffffffu, p[i], 0);
    }

    float m = p[0];
    #pragma unroll
    for (int i = 1; i < 6; i++) m = fmaxf(m, p[i]);
    float att[6], s = 0.f;
    #pragma unroll
    for (int i = 0; i < 6; i++) { att[i] = expf(p[i] - m); s += att[i]; }
    float inv = 1.f / s;
    #pragma unroll
    for (int i = 0; i < 6; i++) att[i] *= inv;

    if (out_att && lane == 0) {
        #pragma unroll
        for (int i = 0; i < 6; i++) out_att[(size_t)r * 6 + i] = att[i];
    }

    #pragma unroll
    for (int kk = 0; kk < 2; kk++) {
        int k = lane + kk * 32;
        float hp = 0.f;
        #pragma unroll
        for (int j = 0; j < 6; j++) {
            int idx = j * 64 + k;
            hp = fmaf(att[j], ch[w][idx % 6][idx / 6], hp);
        }
        out_hp[(size_t)r * F_OUT + k] = hp * (1.0f / 6.0f);
    }
}

// ---------------------------------------------------------------------------
extern "C" void kernel_launch(void* const* d_in, const int* in_sizes, int n_in,
                              void* d_out, int out_size)
{
    const float* x  = (const float*)d_in[0];
    const float* W  = (const float*)d_in[1];
    const float* a  = (const float*)d_in[2];
    const int*   iA  = (const int*)d_in[3];   const float* vA  = (const float*)d_in[4];
    const int*   iP1 = (const int*)d_in[5];   const float* vP1 = (const float*)d_in[6];
    const int*   iP2 = (const int*)d_in[7];   const float* vP2 = (const float*)d_in[8];
    const int*   iP3 = (const int*)d_in[9];   const float* vP3 = (const float*)d_in[10];

    float*  s0;   cudaGetSymbolAddress((void**)&s0,  g_s0);
    __half* s0h;  cudaGetSymbolAddress((void**)&s0h, g_s0h);
    __half* h1h;  cudaGetSymbolAddress((void**)&h1h, g_h1h);
    __half* h2h;  cudaGetSymbolAddress((void**)&h2h, g_h2h);
    float*  acc;  cudaGetSymbolAddress((void**)&acc, g_acc);
    int*    cnt;  cudaGetSymbolAddress((void**)&cnt, g_cnt);
    int*    rp;   cudaGetSymbolAddress((void**)&rp,  g_rowptr);
    int*    rk;   cudaGetSymbolAddress((void**)&rk,  g_rank);
    int2*   eg;   cudaGetSymbolAddress((void**)&eg,  g_edges);
    int*    bs;   cudaGetSymbolAddress((void**)&bs,  g_bsum);
    int*    bsx;  cudaGetSymbolAddress((void**)&bsx, g_bsumx);

    // One-time host-side resources (created on the un-captured correctness
    // call; identical graph topology on every capture thereafter).
    static cudaStream_t s_side = nullptr;
    static cudaEvent_t  ev_fork = nullptr, ev_join = nullptr;
    if (!s_side) {
        cudaStreamCreateWithFlags(&s_side, cudaStreamNonBlocking);
        cudaEventCreateWithFlags(&ev_fork, cudaEventDisableTiming);
        cudaEventCreateWithFlags(&ev_join, cudaEventDisableTiming);
    }

    // Fork: CSR build on side stream, GEMM on main stream (independent work).
    cudaEventRecord(ev_fork, 0);
    cudaStreamWaitEvent(s_side, ev_fork, 0);

    // Main stream: GEMM (produces s0 fp32 + s0h fp16)
    gemm64<<<(N_NODES + 63) / 64, 128>>>(x, W, s0, s0h);

    // Side stream: fused CSR build for all 4 operators
    cudaMemsetAsync(cnt, 0, sizeof(int) * 4 * N_NODES, s_side);
    const dim3 EG((N_EDGES + 255) / 256, 4);
    hist_rank<<<EG, 256, 0, s_side>>>(iA, iP1, iP2, iP3, cnt, rk);
    scan_blocks<<<dim3(NB_SCAN, 4), 256, 0, s_side>>>(cnt, rp, bs);
    scan_bsums<<<1, 128, 0, s_side>>>(bs, bsx);
    scan_addback<<<dim3((N_NODES + 256) / 256, 4), 256, 0, s_side>>>(bsx, rp);
    scatter_edges<<<EG, 256, 0, s_side>>>(iA, iP1, iP2, iP3, vA, vP1, vP2, vP3, rp, rk, eg);

    // Join: SPMMs need both s0h (main) and CSR (side).
    cudaEventRecord(ev_join, s_side);
    cudaStreamWaitEvent(0, ev_join, 0);

    const int SG = (N_NODES * 32 + 255) / 256;
    // Fused: A·s0 -> acc0+h1h, P1..P3 -> acc3..5 (all fp16 gather from s0h)
    spmm_fused4<<<dim3(SG, 4), 256>>>(rp, eg, s0h, acc, h1h);
    // Chain hops 2,3
    spmm_hop<<<SG, 256>>>(rp, eg, h1h, acc + 1 * (size_t)NF, h2h);
    spmm_hop<<<SG, 256>>>(rp, eg, h2h, acc + 2 * (size_t)NF, nullptr);

    float* out = (float*)d_out;
    float* att = (out_size >= N_NODES * F_OUT + N_NODES * 6)
                     ? out + (size_t)N_NODES * F_OUT : nullptr;
    finalize<<<N_NODES / 8, 256>>>(s0, a, out, att);
}